// round 14
// baseline (speedup 1.0000x reference)
#include <cuda_runtime.h>
#include <cuda_bf16.h>
#include <math.h>
#include <stdint.h>

#define BB   2
#define LL   4096
#define DD   1024
#define HH   4
#define DKV  256
#define CC   64
#define NCH  64
#define BH   (BB*HH)
#define BLD  (BB*LL)
#define CT   16
#define TV   16
#define WSZ  ((size_t)DD*DD)
#define SP   260

// ---------------- scratch ----------------
__device__ float g_qp[BLD*DD];
__device__ float g_kp[BLD*DD];
__device__ float g_vp[BLD*DD];
__device__ float g_q [BLD*DD];
__device__ float g_k [BLD*DD];
__device__ float g_v [BLD*DD];
__device__ float g_gp[BLD*DD];
__device__ float g_beta[BH*LL];
__device__ float g_fd[BH*LL];
__device__ float g_sd[BH*LL];
__device__ float g_gF[BH*LL];
__device__ float g_gS[BH*LL];
__device__ float g_psi[BH*NCH];
__device__ float g_gfc[BH*NCH];
__device__ float g_gsc[BH*NCH];
__device__ float g_Tu[(size_t)BH*NCH*CC*DKV];
__device__ float g_Tw[(size_t)BH*NCH*CC*DKV];
__device__ float g_attn[(size_t)BH*NCH*CC*CC];
__device__ float g_o [(size_t)BH*LL*DKV];
__device__ float g_on[BLD*DD];

__device__ __nv_bfloat16 g_xh[(size_t)BLD*DD];
__device__ __nv_bfloat16 g_xl[(size_t)BLD*DD];
__device__ __nv_bfloat16 g_onh[(size_t)BLD*DD];
__device__ __nv_bfloat16 g_onl[(size_t)BLD*DD];
__device__ __nv_bfloat16 g_wth[(size_t)5*DD*DD];
__device__ __nv_bfloat16 g_wtl[(size_t)5*DD*DD];

__device__ __forceinline__ float sigmoidf_(float x){ return 1.f/(1.f+expf(-x)); }
__device__ __forceinline__ float warp_sum(float v){
    #pragma unroll
    for (int m = 16; m > 0; m >>= 1) v += __shfl_xor_sync(0xffffffffu, v, m);
    return v;
}
#define CP_ASYNC16(smaddr, gptr) \
    asm volatile("cp.async.ca.shared.global [%0], [%1], 16;" :: "r"(smaddr), "l"(gptr) : "memory")
#define CP_COMMIT() asm volatile("cp.async.commit_group;" ::: "memory")
#define CP_WAIT0()  asm volatile("cp.async.wait_group 0;" ::: "memory")

// ================= mma.sync split-bf16 GEMM, cp.async double-buffered (R12) =================
#define GK   1024
#define GN   1024
#define SAST 40
#define GBUF (4*128*SAST)
#define GEMM_SMEM (2*GBUF*2)

#define MMA16816(d, a0, a1, a2, a3, b0, b1)                                   \
    asm volatile("mma.sync.aligned.m16n8k16.row.col.f32.bf16.bf16.f32 "       \
        "{%0,%1,%2,%3}, {%4,%5,%6,%7}, {%8,%9}, {%0,%1,%2,%3};"               \
        : "+f"(d[0]), "+f"(d[1]), "+f"(d[2]), "+f"(d[3])                      \
        : "r"(a0), "r"(a1), "r"(a2), "r"(a3), "r"(b0), "r"(b1))

__device__ __forceinline__ void gemm_fill_async(
    __nv_bfloat16* buf, uint32_t buf_sa,
    const __nv_bfloat16* Ah, const __nv_bfloat16* Al,
    const __nv_bfloat16* Bh, const __nv_bfloat16* Bl,
    int m0, int n0, int k0, int tid)
{
    #pragma unroll
    for (int it = 0; it < 2; it++) {
        int i = tid + it*256;
        int r = i >> 2, c = (i & 3) * 8;
        size_t ga = (size_t)(m0 + r)*GK + k0 + c;
        size_t gb = (size_t)(n0 + r)*GK + k0 + c;
        uint32_t so = (uint32_t)((r*SAST + c) * 2);
        CP_ASYNC16(buf_sa + 0*128*SAST*2 + so, Ah + ga);
        CP_ASYNC16(buf_sa + 1*128*SAST*2 + so, Al + ga);
        CP_ASYNC16(buf_sa + 2*128*SAST*2 + so, Bh + gb);
        CP_ASYNC16(buf_sa + 3*128*SAST*2 + so, Bl + gb);
    }
}

__device__ __forceinline__ void gemm_body(
    const __nv_bfloat16* __restrict__ Ah, const __nv_bfloat16* __restrict__ Al,
    const __nv_bfloat16* __restrict__ Bh, const __nv_bfloat16* __restrict__ Bl,
    float* __restrict__ C, __nv_bfloat16* smbase)
{
    int tid = threadIdx.x;
    int warp = tid >> 5, lane = tid & 31;
    int wm = warp >> 1, wn = warp & 1;
    int m0 = blockIdx.y * 128, n0 = blockIdx.x * 128;
    int lg = lane >> 2;
    int lt = lane & 3;
    uint32_t smb_sa = (uint32_t)__cvta_generic_to_shared(smbase);

    float acc[2][8][4];
    #pragma unroll
    for (int mi=0; mi<2; mi++)
        #pragma unroll
        for (int ni=0; ni<8; ni++)
            #pragma unroll
            for (int r=0; r<4; r++) acc[mi][ni][r] = 0.f;

    gemm_fill_async(smbase, smb_sa, Ah, Al, Bh, Bl, m0, n0, 0, tid);
    CP_COMMIT();

    for (int t = 0; t < GK/32; t++) {
        CP_WAIT0();
        __syncthreads();
        __nv_bfloat16* buf = smbase + (t & 1)*GBUF;
        if (t + 1 < GK/32) {
            gemm_fill_async(smbase, smb_sa + ((t+1)&1)*GBUF*2,
                            Ah, Al, Bh, Bl, m0, n0, (t+1)*32, tid);
            CP_COMMIT();
        }
        __nv_bfloat16* sAh = buf;
        __nv_bfloat16* sAl = buf + 128*SAST;
        __nv_bfloat16* sBh = buf + 2*128*SAST;
        __nv_bfloat16* sBl = buf + 3*128*SAST;
        #pragma unroll
        for (int ks = 0; ks < 2; ks++) {
            int kb = ks*16 + lt*2;
            uint32_t aH[2][4], aL[2][4];
            #pragma unroll
            for (int mi = 0; mi < 2; mi++) {
                int row = wm*32 + mi*16 + lg;
                aH[mi][0] = *(uint32_t*)&sAh[row*SAST + kb];
                aH[mi][1] = *(uint32_t*)&sAh[(row+8)*SAST + kb];
                aH[mi][2] = *(uint32_t*)&sAh[row*SAST + kb + 8];
                aH[mi][3] = *(uint32_t*)&sAh[(row+8)*SAST + kb + 8];
                aL[mi][0] = *(uint32_t*)&sAl[row*SAST + kb];
                aL[mi][1] = *(uint32_t*)&sAl[(row+8)*SAST + kb];
                aL[mi][2] = *(uint32_t*)&sAl[row*SAST + kb + 8];
                aL[mi][3] = *(uint32_t*)&sAl[(row+8)*SAST + kb + 8];
            }
            #pragma unroll
            for (int ni = 0; ni < 8; ni++) {
                int nr = wn*64 + ni*8 + lg;
                uint32_t bh0 = *(uint32_t*)&sBh[nr*SAST + kb];
                uint32_t bh1 = *(uint32_t*)&sBh[nr*SAST + kb + 8];
                uint32_t bl0 = *(uint32_t*)&sBl[nr*SAST + kb];
                uint32_t bl1 = *(uint32_t*)&sBl[nr*SAST + kb + 8];
                #pragma unroll
                for (int mi = 0; mi < 2; mi++) {
                    MMA16816(acc[mi][ni], aH[mi][0],aH[mi][1],aH[mi][2],aH[mi][3], bh0, bh1);
                    MMA16816(acc[mi][ni], aH[mi][0],aH[mi][1],aH[mi][2],aH[mi][3], bl0, bl1);
                    MMA16816(acc[mi][ni], aL[mi][0],aL[mi][1],aL[mi][2],aL[mi][3], bh0, bh1);
                }
            }
        }
        __syncthreads();
    }
    #pragma unroll
    for (int mi = 0; mi < 2; mi++) {
        int row = m0 + wm*32 + mi*16 + lg;
        #pragma unroll
        for (int ni = 0; ni < 8; ni++) {
            int col = n0 + wn*64 + ni*8 + lt*2;
            *(float2*)&C[(size_t)row*GN + col]     = make_float2(acc[mi][ni][0], acc[mi][ni][1]);
            *(float2*)&C[(size_t)(row+8)*GN + col] = make_float2(acc[mi][ni][2], acc[mi][ni][3]);
        }
    }
}

__global__ __launch_bounds__(256, 2) void gemm_proj_kernel(
    const __nv_bfloat16* __restrict__ Ah, const __nv_bfloat16* __restrict__ Al)
{
    extern __shared__ float sm[];
    int z = blockIdx.z;
    float* C = (z==0) ? g_qp : (z==1) ? g_kp : (z==2) ? g_vp : g_gp;
    gemm_body(Ah, Al, g_wth + (size_t)z*WSZ, g_wtl + (size_t)z*WSZ, C, (__nv_bfloat16*)sm);
}

__global__ __launch_bounds__(256, 2) void gemm_wo_kernel(
    const __nv_bfloat16* __restrict__ Ah, const __nv_bfloat16* __restrict__ Al,
    float* __restrict__ C)
{
    extern __shared__ float sm[];
    gemm_body(Ah, Al, g_wth + 4*WSZ, g_wtl + 4*WSZ, C, (__nv_bfloat16*)sm);
}

// ---------------- fp32 -> bf16 hi/lo split ----------------
__global__ __launch_bounds__(256) void split_kernel(
    const float* __restrict__ X, __nv_bfloat16* __restrict__ H, __nv_bfloat16* __restrict__ L)
{
    int i = blockIdx.x * 256 + threadIdx.x;
    float4 v = ((const float4*)X)[i];
    __nv_bfloat16 h0 = __float2bfloat16(v.x), h1 = __float2bfloat16(v.y),
                  h2 = __float2bfloat16(v.z), h3 = __float2bfloat16(v.w);
    __nv_bfloat162 hh0 = __nv_bfloat162(h0, h1), hh1 = __nv_bfloat162(h2, h3);
    __nv_bfloat162 ll0 = __nv_bfloat162(__float2bfloat16(v.x - __bfloat162float(h0)),
                                        __float2bfloat16(v.y - __bfloat162float(h1)));
    __nv_bfloat162 ll1 = __nv_bfloat162(__float2bfloat16(v.z - __bfloat162float(h2)),
                                        __float2bfloat16(v.w - __bfloat162float(h3)));
    ((__nv_bfloat162*)H)[i*2]   = hh0;
    ((__nv_bfloat162*)H)[i*2+1] = hh1;
    ((__nv_bfloat162*)L)[i*2]   = ll0;
    ((__nv_bfloat162*)L)[i*2+1] = ll1;
}

// ---------------- fused weight transpose+split ----------------
__global__ __launch_bounds__(256) void wtrans_all_kernel(
    const float* __restrict__ W0, const float* __restrict__ W1,
    const float* __restrict__ W2, const float* __restrict__ W3,
    const float* __restrict__ W4)
{
    __shared__ float t[32][33];
    int z = blockIdx.z;
    const float* W = (z==0)?W0 : (z==1)?W1 : (z==2)?W2 : (z==3)?W3 : W4;
    __nv_bfloat16* Th = g_wth + (size_t)z*WSZ;
    __nv_bfloat16* Tl = g_wtl + (size_t)z*WSZ;
    int n0 = blockIdx.x*32, k0 = blockIdx.y*32;
    int tx = threadIdx.x & 31, ty0 = threadIdx.x >> 5;
    #pragma unroll
    for (int r = 0; r < 4; r++) {
        int ty = ty0 + r*8;
        t[ty][tx] = W[(size_t)(k0+ty)*DD + n0 + tx];
    }
    __syncthreads();
    #pragma unroll
    for (int r = 0; r < 4; r++) {
        int ty = ty0 + r*8;
        float v = t[tx][ty];
        __nv_bfloat16 h = __float2bfloat16(v);
        Th[(size_t)(n0+ty)*DD + k0+tx] = h;
        Tl[(size_t)(n0+ty)*DD + k0+tx] = __float2bfloat16(v - __bfloat162float(h));
    }
}

// ---------------- fused depthwise conv ----------------
__global__ __launch_bounds__(256) void conv_all_kernel(
    const float* __restrict__ wq, const float* __restrict__ bq,
    const float* __restrict__ wk, const float* __restrict__ bk,
    const float* __restrict__ wv, const float* __restrict__ bv)
{
    __shared__ float red[8];
    int which = blockIdx.y;
    const float* P    = (which==0) ? g_qp : (which==1) ? g_kp : g_vp;
    float*       outp = (which==0) ? g_q  : (which==1) ? g_k  : g_v;
    const float* w    = (which==0) ? wq : (which==1) ? wk : wv;
    const float* bias = (which==0) ? bq : (which==1) ? bk : bv;
    int do_norm = (which < 2);
    int bid = blockIdx.x;
    int h = bid & 3; int bl = bid >> 2;
    int b = bl / LL, l = bl % LL;
    int ch = h*DKV + threadIdx.x;
    float4 wvv = *(const float4*)(w + (size_t)ch*4);
    const float wj[4] = {wvv.x, wvv.y, wvv.z, wvv.w};
    float val = bias[ch];
    #pragma unroll
    for (int j=0;j<4;j++) {
        int lp = l + j - 2;
        float xv = (lp>=0 && lp<LL) ? P[((size_t)b*LL+lp)*DD + ch] : 0.f;
        val += wj[j]*xv;
    }
    val = val * sigmoidf_(val);
    if (do_norm) {
        float s = warp_sum(val*val);
        if ((threadIdx.x & 31) == 0) red[threadIdx.x >> 5] = s;
        __syncthreads();
        if (threadIdx.x < 32) {
            float t = (threadIdx.x < 8) ? red[threadIdx.x] : 0.f;
            #pragma unroll
            for (int m = 4; m > 0; m >>= 1) t += __shfl_xor_sync(0xffffffffu, t, m);
            if (threadIdx.x == 0) red[0] = t;
        }
        __syncthreads();
        val = val / fmaxf(sqrtf(red[0]), 1e-6f);
    }
    outp[((size_t)b*LL+l)*DD + ch] = val;
}

// ---------------- 5 tiny head projections ----------------
__global__ __launch_bounds__(256) void smallproj_kernel(
    const float* __restrict__ x,
    const float* __restrict__ Wb, const float* __restrict__ Wfd,
    const float* __restrict__ bfd, const float* __restrict__ fd_bias,
    const float* __restrict__ Wsd, const float* __restrict__ bsd, const float* __restrict__ sd_bias,
    const float* __restrict__ Wfg, const float* __restrict__ Wsg)
{
    __shared__ float red[8][20];
    int bl = blockIdx.x;
    int tid = threadIdx.x;
    float acc[20];
    #pragma unroll
    for (int j=0;j<20;j++) acc[j]=0.f;
    for (int d = tid; d < DD; d += 256) {
        float xv = x[(size_t)bl*DD + d];
        #pragma unroll
        for (int h=0; h<4; h++) {
            acc[0*4+h] += xv * Wb [d*4+h];
            acc[1*4+h] += xv * Wfd[d*4+h];
            acc[2*4+h] += xv * Wsd[d*4+h];
            acc[3*4+h] += xv * Wfg[d*4+h];
            acc[4*4+h] += xv * Wsg[d*4+h];
        }
    }
    #pragma unroll
    for (int j=0;j<20;j++) {
        float s = warp_sum(acc[j]);
        if ((tid & 31) == 0) red[tid >> 5][j] = s;
    }
    __syncthreads();
    if (tid < 20) {
        float s = 0.f;
        #pragma unroll
        for (int w = 0; w < 8; w++) s += red[w][tid];
        int p = tid/4, h = tid%4;
        int b = bl / LL, l = bl % LL;
        size_t oi = ((size_t)(b*HH + h))*LL + l;
        if      (p==0) g_beta[oi] = sigmoidf_(s);
        else if (p==1) g_fd[oi]   = sigmoidf_(s + bfd[h] + fd_bias[h]);
        else if (p==2) g_sd[oi]   = sigmoidf_(s + bsd[h] + sd_bias[h]);
        else if (p==3) g_gF[oi]   = sigmoidf_(s);
        else           g_gS[oi]   = sigmoidf_(s);
    }
}

// ---------------- psi (R12) ----------------
__global__ __launch_bounds__(256) void psi_kernel(
    const float* __restrict__ W_bil, const float* __restrict__ temp,
    const float* __restrict__ fw1, const float* __restrict__ fb1,
    const float* __restrict__ fw2, const float* __restrict__ fb2)
{
    extern __shared__ float sm[];
    float* kcs  = sm;
    float* us   = sm + 16384;
    float* flux = sm + 32768;
    float* red  = sm + 32768 + 520;
    int bhn = blockIdx.x;
    int n = bhn % NCH; int bh = bhn / NCH; int b = bh / HH, h = bh % HH;
    int tid = threadIdx.x;
    int l0 = n*CC;
    for (int i = tid; i < CC*DKV; i += 256) {
        int c = i >> 8, d = i & 255;
        size_t gi = ((size_t)b*LL + l0 + c)*DD + h*DKV + d;
        float bta = g_beta[(size_t)bh*LL + l0 + c];
        kcs[i] = g_k[gi];
        us[i]  = g_v[gi] * bta;
    }
    __syncthreads();
    int d = tid;
    float km=0.f, um=0.f;
    for (int c=0;c<CC;c++){ km += kcs[c*256+d]; um += us[c*256+d]; }
    flux[d]     = km * (1.f/CC);
    flux[256+d] = um * (1.f/CC);
    const float* W = W_bil + (size_t)h*DKV*DKV;
    float bsum = 0.f;
    for (int c0 = 0; c0 < CC; c0 += 16) {
        float dot[16];
        #pragma unroll
        for (int c2=0;c2<16;c2++) dot[c2]=0.f;
        for (int k4 = 0; k4 < 64; k4++) {
            float wv0 = W[(size_t)(k4*4+0)*DKV + d];
            float wv1 = W[(size_t)(k4*4+1)*DKV + d];
            float wv2 = W[(size_t)(k4*4+2)*DKV + d];
            float wv3 = W[(size_t)(k4*4+3)*DKV + d];
            #pragma unroll
            for (int c2=0;c2<16;c2++){
                float4 kc = *(float4*)&kcs[(c0+c2)*256 + k4*4];
                dot[c2] += kc.x*wv0 + kc.y*wv1 + kc.z*wv2 + kc.w*wv3;
            }
        }
        #pragma unroll
        for (int c2=0;c2<16;c2++) bsum += dot[c2] * us[(c0+c2)*256 + d];
    }
    red[tid] = bsum; __syncthreads();
    for (int s=128;s>0;s>>=1){ if(tid<s) red[tid]+=red[tid+s]; __syncthreads(); }
    if (tid==0) flux[512] = red[0] / (temp[h] * (float)CC);
    __syncthreads();
    float hj = 0.f;
    if (tid < 128) {
        float a = fb1[tid];
        for (int i=0;i<513;i++) a += flux[i]*fw1[i*128+tid];
        a = a * sigmoidf_(a);
        hj = a * fw2[tid];
    }
    red[tid] = hj; __syncthreads();
    for (int s=128;s>0;s>>=1){ if(tid<s) red[tid]+=red[tid+s]; __syncthreads(); }
    if (tid == 0) {
        float p = sigmoidf_(red[0] + fb2[0]);
        g_psi[bhn] = fminf(fmaxf(p, 0.01f), 0.99f);
    }
    __syncthreads();
    red[tid] = (tid<CC) ? logf(g_fd[(size_t)bh*LL + l0 + tid]) : 0.f;
    __syncthreads();
    for (int s=128;s>0;s>>=1){ if(tid<s) red[tid]+=red[tid+s]; __syncthreads(); }
    if (tid==0) g_gfc[bhn] = expf(red[0]);
    __syncthreads();
    red[tid] = (tid<CC) ? logf(g_sd[(size_t)bh*LL + l0 + tid]) : 0.f;
    __syncthreads();
    for (int s=128;s>0;s>>=1){ if(tid<s) red[tid]+=red[tid+s]; __syncthreads(); }
    if (tid==0) g_gsc[bhn] = expf(red[0]);
}

// ---------------- tfactor v4: 512 threads, concurrent Tu/Tw solves ----------------
// smem: kT[256][68] + As[64][68] + ucl[2][256][68] + betas[64] = 226.5 KB
__global__ __launch_bounds__(512) void tfactor_kernel()
{
    extern __shared__ float sm[];
    float* kT    = sm;                      // [256][68]
    float* As    = sm + 256*68;             // [64][68]
    float* ucl   = As + 64*68;              // [2][256][68]
    float* betas = ucl + 2*256*68;          // [64]
    int bhn = blockIdx.x;
    int n = bhn % NCH, bh = bhn/NCH, b = bh/HH, h = bh%HH;
    int l0 = n*CC, tid = threadIdx.x;
    int tc2 = tid >> 4, td = tid & 15;      // 32 x 16 grid -> 2x4 tiles

    for (int i = tid; i < CC*DKV; i += 512) {
        int c = i >> 8, dk = i & 255;
        kT[dk*68 + c] = g_k[((size_t)b*LL + l0 + c)*DD + h*DKV + dk];
    }
    if (tid < CC) betas[tid] = g_beta[(size_t)bh*LL + l0 + tid];
    __syncthreads();
    // A = tril(beta * k k^T, -1), 2x4 register tiles
    {
        float a2[2][4];
        #pragma unroll
        for (int i=0;i<2;i++)
            #pragma unroll
            for (int j=0;j<4;j++) a2[i][j]=0.f;
        for (int k=0;k<DKV;k++){
            float av[2], bv[4];
            #pragma unroll
            for (int i=0;i<2;i++) av[i] = kT[k*68 + tc2*2+i];
            #pragma unroll
            for (int j=0;j<4;j++) bv[j] = kT[k*68 + td*4+j];
            #pragma unroll
            for (int i=0;i<2;i++)
                #pragma unroll
                for (int j=0;j<4;j++) a2[i][j] += av[i]*bv[j];
        }
        #pragma unroll
        for (int i=0;i<2;i++)
            #pragma unroll
            for (int j=0;j<4;j++){
                int c = tc2*2+i, dc = td*4+j;
                As[c*68+dc] = (dc < c) ? betas[c]*a2[i][j] : 0.f;
            }
    }
    __syncthreads();
    // concurrent forward substitutions: half 0 -> Tu, half 1 -> Tw
    {
        int half = tid >> 8;
        int d = tid & 255;
        float* uc = &ucl[half*256*68 + d*68];
        if (half == 0) {
            const float* vb = g_v + ((size_t)b*LL+l0)*DD + h*DKV + d;
            for (int c=0;c<CC;c++) uc[c] = vb[(size_t)c*DD] * betas[c];
        } else {
            for (int c=0;c<CC;c++) uc[c] = betas[c]*kT[d*68+c];
        }
        for (int c=1;c<CC;c++){
            const float* Ar = &As[c*68];
            float s = 0.f;
            int cq = c >> 2;
            for (int mq=0; mq<cq; mq++){
                float4 a = *(float4*)&Ar[mq*4];
                float4 u = *(float4*)&uc[mq*4];
                s += a.x*u.x + a.y*u.y + a.z*u.z + a.w*u.w;
            }
            for (int m=cq*4; m<c; m++) s += Ar[m]*uc[m];
            uc[c] -= s;
        }
        float* dst = (half == 0) ? g_Tu : g_Tw;
        for (int c=0;c<CC;c++) dst[((size_t)bhn*CC + c)*DKV + d] = uc[c];
    }
    __syncthreads();
    // attn = tril(q k^T): q staged in 4 slices through As, 2x4 tiles
    {
        float t2[2][4];
        #pragma unroll
        for (int i=0;i<2;i++)
            #pragma unroll
            for (int j=0;j<4;j++) t2[i][j]=0.f;
        for (int ks=0; ks<4; ks++){
            __syncthreads();
            for (int i = tid; i < CC*64; i += 512){
                int c = i>>6, kk = i&63;
                As[c*68+kk] = g_q[((size_t)b*LL+l0+c)*DD + h*DKV + ks*64+kk];
            }
            __syncthreads();
            for (int kk=0;kk<64;kk++){
                int k = ks*64+kk;
                float av[2], bv[4];
                #pragma unroll
                for (int i=0;i<2;i++) av[i] = As[(tc2*2+i)*68 + kk];
                #pragma unroll
                for (int j=0;j<4;j++) bv[j] = kT[k*68 + td*4+j];
                #pragma unroll
                for (int i=0;i<2;i++)
                    #pragma unroll
                    for (int j=0;j<4;j++) t2[i][j] += av[i]*bv[j];
            }
        }
        #pragma unroll
        for (int i=0;i<2;i++)
            #pragma unroll
            for (int j=0;j<4;j++){
                int c = tc2*2+i, dc = td*4+j;
                g_attn[(size_t)bhn*CC*CC + c*CC + dc] = (dc <= c) ? t2[i][j] : 0.f;
            }
    }
}

// ---------------- scan v4: 512 threads, v-major state ----------------
#define ACC2(Cm) { float s0=sf0.Cm+ss0.Cm, s1=sf1.Cm+ss1.Cm;         \
    au0 -= tw.Cm*s0; au1 -= tw.Cm*s1;                                \
    af0 += q.Cm*sf0.Cm; af1 += q.Cm*sf1.Cm;                          \
    as0 += q.Cm*ss0.Cm; as1 += q.Cm*ss1.Cm; }

__global__ __launch_bounds__(512) void scan_kernel()
{
    extern __shared__ float sm[];
    float* SfT = sm;                    // [16][260]
    float* SsT = SfT + 16*SP;           // [16][260]
    float* Twt = SsT + 16*SP;           // [64][68]
    float* qt  = Twt + 64*68;           // [64][68]
    float* Uc  = qt + 64*68;            // [64][20]
    int tid = threadIdx.x;
    int bh = blockIdx.x / CT, tile = blockIdx.x % CT;
    int b = bh / HH, h = bh % HH;
    int col0 = tile * TV;
    int cA = (tid & 7) * 2;             // v pair
    int rA = tid >> 3;                  // c row (0..63)
    int vp = (tid & 7) * 2;             // kU: v pair
    int ks1 = tid >> 3;                 // kU: k within slice (0..63)
    for (int i = tid; i < 16*SP; i += 512) { SfT[i]=0.f; SsT[i]=0.f; }
    __syncthreads();
    const float* qg = g_q + (size_t)b*LL*DD + h*DKV;
    const float* kg = g_k + (size_t)b*LL*DD + h*DKV;
    for (int n = 0; n < NCH; n++) {
        int bhn = bh*NCH + n;
        float psi = g_psi[bhn], gf = g_gfc[bhn], gs = g_gsc[bhn];
        size_t tbase = (size_t)bhn*CC*DKV;
        float au0=0,au1=0, af0=0,af1=0, as0=0,as1=0;
        // ---- phase A over 4 k-slices
        for (int kb = 0; kb < 4; kb++) {
            __syncthreads();
            for (int i = tid; i < 1024; i += 512) {
                int c = i >> 4, kq = (i & 15) * 4;
                *(float4*)&Twt[c*68+kq] = *(const float4*)&g_Tw[tbase + (size_t)c*DKV + kb*64 + kq];
                *(float4*)&qt [c*68+kq] = *(const float4*)&qg[(size_t)(n*CC+c)*DD + kb*64 + kq];
            }
            __syncthreads();
            #pragma unroll 4
            for (int kq = 0; kq < 16; kq++) {
                int kg4 = kb*64 + kq*4;
                float4 sf0 = *(float4*)&SfT[cA*SP + kg4];
                float4 sf1 = *(float4*)&SfT[(cA+1)*SP + kg4];
                float4 ss0 = *(float4*)&SsT[cA*SP + kg4];
                float4 ss1 = *(float4*)&SsT[(cA+1)*SP + kg4];
                float4 tw  = *(float4*)&Twt[rA*68 + kq*4];
                float4 q   = *(float4*)&qt[rA*68 + kq*4];
                ACC2(x) ACC2(y) ACC2(z) ACC2(w)
            }
        }
        __syncthreads();
        // ---- u_corr into Uc[c][v]
        {
            float t0 = g_Tu[tbase + (size_t)rA*DKV + col0+cA]   + au0;
            float t1 = g_Tu[tbase + (size_t)rA*DKV + col0+cA+1] + au1;
            Uc[rA*20 + cA]   = t0;
            Uc[rA*20 + cA+1] = t1;
        }
        // load attn into Twt
        for (int i = tid; i < 1024; i += 512) {
            int c = i >> 4, kq = (i & 15) * 4;
            *(float4*)&Twt[c*68+kq] = *(const float4*)&g_attn[(size_t)bhn*CC*CC + c*CC + kq];
        }
        __syncthreads();
        // ---- o_intra + output
        {
            float oi0=0, oi1=0;
            #pragma unroll 4
            for (int dq = 0; dq < 16; dq++) {
                float4 a = *(float4*)&Twt[rA*68 + dq*4];
                float2 u0 = *(float2*)&Uc[(dq*4+0)*20 + cA];
                float2 u1 = *(float2*)&Uc[(dq*4+1)*20 + cA];
                float2 u2 = *(float2*)&Uc[(dq*4+2)*20 + cA];
                float2 u3 = *(float2*)&Uc[(dq*4+3)*20 + cA];
                oi0 += a.x*u0.x + a.y*u1.x + a.z*u2.x + a.w*u3.x;
                oi1 += a.x*u0.y + a.y*u1.y + a.z*u2.y + a.w*u3.y;
            }
            int l = n*CC + rA;
            float gFv = g_gF[(size_t)bh*LL + l];
            float gSv = g_gS[(size_t)bh*LL + l];
            *(float2*)&g_o[((size_t)bh*LL + l)*DKV + col0 + cA] =
                make_float2(gFv*af0 + gSv*as0 + oi0, gFv*af1 + gSv*as1 + oi1);
        }
        // ---- kU + state update (k sliced by 64)
        float psn = 1.f - psi;
        for (int kb = 0; kb < 4; kb++) {
            __syncthreads();
            for (int i = tid; i < 1024; i += 512) {
                int c = i >> 4, kq = (i & 15) * 4;
                *(float4*)&qt[c*68+kq] = *(const float4*)&kg[(size_t)(n*CC+c)*DD + kb*64 + kq];
            }
            __syncthreads();
            float kuA=0, kuB=0;
            #pragma unroll 8
            for (int c = 0; c < CC; c++) {
                float kv = qt[c*68 + ks1];
                float2 u2 = *(float2*)&Uc[c*20 + vp];
                kuA += kv*u2.x; kuB += kv*u2.y;
            }
            int kglob = kb*64 + ks1;
            int i0 = (vp+0)*SP + kglob;
            int i1 = (vp+1)*SP + kglob;
            SfT[i0] = gf*SfT[i0] + psn*kuA;
            SfT[i1] = gf*SfT[i1] + psn*kuB;
            SsT[i0] = gs*SsT[i0] + psi*kuA;
            SsT[i1] = gs*SsT[i1] + psi*kuB;
        }
        __syncthreads();
    }
}

// ---------------- gated RMSNorm ----------------
__global__ __launch_bounds__(256) void onorm_kernel(const float* __restrict__ onw)
{
    __shared__ float red[8];
    int bid = blockIdx.x;
    int h = bid & 3; int bl = bid >> 2;
    int b = bl / LL, l = bl % LL;
    int v = threadIdx.x;
    float val = g_o[(((size_t)(b*HH+h))*LL + l)*DKV + v];
    float s = warp_sum(val*val);
    if ((v & 31) == 0) red[v >> 5] = s;
    __syncthreads();
    if (v < 32) {
        float t = (v < 8) ? red[v] : 0.f;
        #pragma unroll
        for (int m = 4; m > 0; m >>= 1) t += __shfl_xor_sync(0xffffffffu, t, m);
        if (v == 0) red[0] = t;
    }
    __syncthreads();
    float scale = rsqrtf(red[0]*(1.f/DKV) + 1e-5f);
    float gv = g_gp[(size_t)bl*DD + h*DKV + v];
    g_on[(size_t)bl*DD + h*DKV + v] = val*scale*onw[v]*sigmoidf_(gv);
}

// ---------------- launch ----------------
extern "C" void kernel_launch(void* const* d_in, const int* in_sizes, int n_in,
                              void* d_out, int out_size)
{
    const float* x     = (const float*)d_in[0];
    const float* Wq    = (const float*)d_in[1];
    const float* Wk    = (const float*)d_in[2];
    const float* Wv    = (const float*)d_in[3];
    const float* cq_w  = (const float*)d_in[4];
    const float* cq_b  = (const float*)d_in[5];
    const float* ck_w  = (const float*)d_in[6];
    const float* ck_b  = (const float*)d_in[7];
    const float* cv_w  = (const float*)d_in[8];
    const float* cv_b  = (const float*)d_in[9];
    const float* Wb    = (const float*)d_in[10];
    const float* Wfd   = (const float*)d_in[11];
    const float* bfd   = (const float*)d_in[12];
    const float* fdb   = (const float*)d_in[13];
    const float* Wsd   = (const float*)d_in[14];
    const float* bsd   = (const float*)d_in[15];
    const float* sdb   = (const float*)d_in[16];
    const float* W_bil = (const float*)d_in[17];
    const float* temp  = (const float*)d_in[18];
    const float* fw1   = (const float*)d_in[19];
    const float* fb1   = (const float*)d_in[20];
    const float* fw2   = (const float*)d_in[21];
    const float* fb2   = (const float*)d_in[22];
    const float* Wfg   = (const float*)d_in[23];
    const float* Wsg   = (const float*)d_in[24];
    const float* Wg    = (const float*)d_in[25];
    const float* onw   = (const float*)d_in[26];
    const float* Wo    = (const float*)d_in[27];
    float* out = (float*)d_out;

    float *p_on;
    __nv_bfloat16 *p_xh,*p_xl,*p_onh,*p_onl;
    cudaGetSymbolAddress((void**)&p_on, g_on);
    cudaGetSymbolAddress((void**)&p_xh, g_xh);
    cudaGetSymbolAddress((void**)&p_xl, g_xl);
    cudaGetSymbolAddress((void**)&p_onh, g_onh);
    cudaGetSymbolAddress((void**)&p_onl, g_onl);

    int psi_smem  = (16384+16384+520+256)*4;
    int tf_smem   = (256*68 + 64*68 + 2*256*68 + 64)*4;
    int scan_smem = (2*16*SP + 2*64*68 + 64*20)*4;
    cudaFuncSetAttribute(psi_kernel,      cudaFuncAttributeMaxDynamicSharedMemorySize, psi_smem);
    cudaFuncSetAttribute(tfactor_kernel,  cudaFuncAttributeMaxDynamicSharedMemorySize, tf_smem);
    cudaFuncSetAttribute(scan_kernel,     cudaFuncAttributeMaxDynamicSharedMemorySize, scan_smem);
    cudaFuncSetAttribute(gemm_proj_kernel, cudaFuncAttributeMaxDynamicSharedMemorySize, GEMM_SMEM);
    cudaFuncSetAttribute(gemm_wo_kernel,   cudaFuncAttributeMaxDynamicSharedMemorySize, GEMM_SMEM);

    split_kernel<<<(BLD*DD/4)/256, 256>>>(x, p_xh, p_xl);
    dim3 wtg(DD/32, DD/32, 5);
    wtrans_all_kernel<<<wtg, 256>>>(Wq, Wk, Wv, Wg, Wo);
    dim3 gp(GN/128, BLD/128, 4);
    gemm_proj_kernel<<<gp, 256, GEMM_SMEM>>>(p_xh, p_xl);
    dim3 cg(BLD*HH, 3);
    conv_all_kernel<<<cg, 256>>>(cq_w, cq_b, ck_w, ck_b, cv_w, cv_b);
    smallproj_kernel<<<BLD, 256>>>(x, Wb, Wfd, bfd, fdb, Wsd, bsd, sdb, Wfg, Wsg);
    tfactor_kernel<<<BH*NCH, 512, tf_smem>>>();
    psi_kernel<<<BH*NCH, 256, psi_smem>>>(W_bil, temp, fw1, fb1, fw2, fb2);
    scan_kernel<<<BH*CT, 512, scan_smem>>>();
    onorm_kernel<<<BLD*HH, 256>>>(onw);
    split_kernel<<<(BLD*DD/4)/256, 256>>>(p_on, p_onh, p_onl);
    dim3 gw(GN/128, BLD/128);
    gemm_wo_kernel<<<gw, 256, GEMM_SMEM>>>(p_onh, p_onl, out);
}

// round 15
// speedup vs baseline: 1.1099x; 1.1099x over previous
#include <cuda_runtime.h>
#include <cuda_bf16.h>
#include <math.h>
#include <stdint.h>

#define BB   2
#define LL   4096
#define DD   1024
#define HH   4
#define DKV  256
#define CC   64
#define NCH  64
#define BH   (BB*HH)
#define BLD  (BB*LL)
#define CT   16
#define TV   16
#define WSZ  ((size_t)DD*DD)
#define SP   260

// ---------------- scratch ----------------
__device__ float g_qp[BLD*DD];
__device__ float g_kp[BLD*DD];
__device__ float g_vp[BLD*DD];
__device__ float g_q [BLD*DD];
__device__ float g_k [BLD*DD];
__device__ float g_v [BLD*DD];
__device__ float g_gp[BLD*DD];
__device__ float g_beta[BH*LL];
__device__ float g_fd[BH*LL];
__device__ float g_sd[BH*LL];
__device__ float g_gF[BH*LL];
__device__ float g_gS[BH*LL];
__device__ float g_psi[BH*NCH];
__device__ float g_gfc[BH*NCH];
__device__ float g_gsc[BH*NCH];
__device__ float g_Tu[(size_t)BH*NCH*CC*DKV];
__device__ float g_Tw[(size_t)BH*NCH*CC*DKV];
__device__ float g_attn[(size_t)BH*NCH*CC*CC];
__device__ float g_o [(size_t)BH*LL*DKV];

__device__ __nv_bfloat16 g_xh[(size_t)BLD*DD];
__device__ __nv_bfloat16 g_xl[(size_t)BLD*DD];
__device__ __nv_bfloat16 g_onh[(size_t)BLD*DD];
__device__ __nv_bfloat16 g_onl[(size_t)BLD*DD];
__device__ __nv_bfloat16 g_wth[(size_t)5*DD*DD];
__device__ __nv_bfloat16 g_wtl[(size_t)5*DD*DD];

__device__ __forceinline__ float sigmoidf_(float x){ return 1.f/(1.f+expf(-x)); }
__device__ __forceinline__ float warp_sum(float v){
    #pragma unroll
    for (int m = 16; m > 0; m >>= 1) v += __shfl_xor_sync(0xffffffffu, v, m);
    return v;
}
#define CP_ASYNC16(smaddr, gptr) \
    asm volatile("cp.async.ca.shared.global [%0], [%1], 16;" :: "r"(smaddr), "l"(gptr) : "memory")
#define CP_COMMIT() asm volatile("cp.async.commit_group;" ::: "memory")
#define CP_WAIT0()  asm volatile("cp.async.wait_group 0;" ::: "memory")

// ================= mma.sync split-bf16 GEMM, cp.async double-buffered (R12) =================
#define GK   1024
#define GN   1024
#define SAST 40
#define GBUF (4*128*SAST)
#define GEMM_SMEM (2*GBUF*2)

#define MMA16816(d, a0, a1, a2, a3, b0, b1)                                   \
    asm volatile("mma.sync.aligned.m16n8k16.row.col.f32.bf16.bf16.f32 "       \
        "{%0,%1,%2,%3}, {%4,%5,%6,%7}, {%8,%9}, {%0,%1,%2,%3};"               \
        : "+f"(d[0]), "+f"(d[1]), "+f"(d[2]), "+f"(d[3])                      \
        : "r"(a0), "r"(a1), "r"(a2), "r"(a3), "r"(b0), "r"(b1))

__device__ __forceinline__ void gemm_fill_async(
    __nv_bfloat16* buf, uint32_t buf_sa,
    const __nv_bfloat16* Ah, const __nv_bfloat16* Al,
    const __nv_bfloat16* Bh, const __nv_bfloat16* Bl,
    int m0, int n0, int k0, int tid)
{
    #pragma unroll
    for (int it = 0; it < 2; it++) {
        int i = tid + it*256;
        int r = i >> 2, c = (i & 3) * 8;
        size_t ga = (size_t)(m0 + r)*GK + k0 + c;
        size_t gb = (size_t)(n0 + r)*GK + k0 + c;
        uint32_t so = (uint32_t)((r*SAST + c) * 2);
        CP_ASYNC16(buf_sa + 0*128*SAST*2 + so, Ah + ga);
        CP_ASYNC16(buf_sa + 1*128*SAST*2 + so, Al + ga);
        CP_ASYNC16(buf_sa + 2*128*SAST*2 + so, Bh + gb);
        CP_ASYNC16(buf_sa + 3*128*SAST*2 + so, Bl + gb);
    }
}

__device__ __forceinline__ void gemm_body(
    const __nv_bfloat16* __restrict__ Ah, const __nv_bfloat16* __restrict__ Al,
    const __nv_bfloat16* __restrict__ Bh, const __nv_bfloat16* __restrict__ Bl,
    float* __restrict__ C, __nv_bfloat16* smbase)
{
    int tid = threadIdx.x;
    int warp = tid >> 5, lane = tid & 31;
    int wm = warp >> 1, wn = warp & 1;
    int m0 = blockIdx.y * 128, n0 = blockIdx.x * 128;
    int lg = lane >> 2;
    int lt = lane & 3;
    uint32_t smb_sa = (uint32_t)__cvta_generic_to_shared(smbase);

    float acc[2][8][4];
    #pragma unroll
    for (int mi=0; mi<2; mi++)
        #pragma unroll
        for (int ni=0; ni<8; ni++)
            #pragma unroll
            for (int r=0; r<4; r++) acc[mi][ni][r] = 0.f;

    gemm_fill_async(smbase, smb_sa, Ah, Al, Bh, Bl, m0, n0, 0, tid);
    CP_COMMIT();

    for (int t = 0; t < GK/32; t++) {
        CP_WAIT0();
        __syncthreads();
        __nv_bfloat16* buf = smbase + (t & 1)*GBUF;
        if (t + 1 < GK/32) {
            gemm_fill_async(smbase, smb_sa + ((t+1)&1)*GBUF*2,
                            Ah, Al, Bh, Bl, m0, n0, (t+1)*32, tid);
            CP_COMMIT();
        }
        __nv_bfloat16* sAh = buf;
        __nv_bfloat16* sAl = buf + 128*SAST;
        __nv_bfloat16* sBh = buf + 2*128*SAST;
        __nv_bfloat16* sBl = buf + 3*128*SAST;
        #pragma unroll
        for (int ks = 0; ks < 2; ks++) {
            int kb = ks*16 + lt*2;
            uint32_t aH[2][4], aL[2][4];
            #pragma unroll
            for (int mi = 0; mi < 2; mi++) {
                int row = wm*32 + mi*16 + lg;
                aH[mi][0] = *(uint32_t*)&sAh[row*SAST + kb];
                aH[mi][1] = *(uint32_t*)&sAh[(row+8)*SAST + kb];
                aH[mi][2] = *(uint32_t*)&sAh[row*SAST + kb + 8];
                aH[mi][3] = *(uint32_t*)&sAh[(row+8)*SAST + kb + 8];
                aL[mi][0] = *(uint32_t*)&sAl[row*SAST + kb];
                aL[mi][1] = *(uint32_t*)&sAl[(row+8)*SAST + kb];
                aL[mi][2] = *(uint32_t*)&sAl[row*SAST + kb + 8];
                aL[mi][3] = *(uint32_t*)&sAl[(row+8)*SAST + kb + 8];
            }
            #pragma unroll
            for (int ni = 0; ni < 8; ni++) {
                int nr = wn*64 + ni*8 + lg;
                uint32_t bh0 = *(uint32_t*)&sBh[nr*SAST + kb];
                uint32_t bh1 = *(uint32_t*)&sBh[nr*SAST + kb + 8];
                uint32_t bl0 = *(uint32_t*)&sBl[nr*SAST + kb];
                uint32_t bl1 = *(uint32_t*)&sBl[nr*SAST + kb + 8];
                #pragma unroll
                for (int mi = 0; mi < 2; mi++) {
                    MMA16816(acc[mi][ni], aH[mi][0],aH[mi][1],aH[mi][2],aH[mi][3], bh0, bh1);
                    MMA16816(acc[mi][ni], aH[mi][0],aH[mi][1],aH[mi][2],aH[mi][3], bl0, bl1);
                    MMA16816(acc[mi][ni], aL[mi][0],aL[mi][1],aL[mi][2],aL[mi][3], bh0, bh1);
                }
            }
        }
        __syncthreads();
    }
    #pragma unroll
    for (int mi = 0; mi < 2; mi++) {
        int row = m0 + wm*32 + mi*16 + lg;
        #pragma unroll
        for (int ni = 0; ni < 8; ni++) {
            int col = n0 + wn*64 + ni*8 + lt*2;
            *(float2*)&C[(size_t)row*GN + col]     = make_float2(acc[mi][ni][0], acc[mi][ni][1]);
            *(float2*)&C[(size_t)(row+8)*GN + col] = make_float2(acc[mi][ni][2], acc[mi][ni][3]);
        }
    }
}

__global__ __launch_bounds__(256, 2) void gemm_proj_kernel(
    const __nv_bfloat16* __restrict__ Ah, const __nv_bfloat16* __restrict__ Al)
{
    extern __shared__ float sm[];
    int z = blockIdx.z;
    float* C = (z==0) ? g_qp : (z==1) ? g_kp : (z==2) ? g_vp : g_gp;
    gemm_body(Ah, Al, g_wth + (size_t)z*WSZ, g_wtl + (size_t)z*WSZ, C, (__nv_bfloat16*)sm);
}

__global__ __launch_bounds__(256, 2) void gemm_wo_kernel(
    const __nv_bfloat16* __restrict__ Ah, const __nv_bfloat16* __restrict__ Al,
    float* __restrict__ C)
{
    extern __shared__ float sm[];
    gemm_body(Ah, Al, g_wth + 4*WSZ, g_wtl + 4*WSZ, C, (__nv_bfloat16*)sm);
}

// ---------------- fused weight transpose+split ----------------
__global__ __launch_bounds__(256) void wtrans_all_kernel(
    const float* __restrict__ W0, const float* __restrict__ W1,
    const float* __restrict__ W2, const float* __restrict__ W3,
    const float* __restrict__ W4)
{
    __shared__ float t[32][33];
    int z = blockIdx.z;
    const float* W = (z==0)?W0 : (z==1)?W1 : (z==2)?W2 : (z==3)?W3 : W4;
    __nv_bfloat16* Th = g_wth + (size_t)z*WSZ;
    __nv_bfloat16* Tl = g_wtl + (size_t)z*WSZ;
    int n0 = blockIdx.x*32, k0 = blockIdx.y*32;
    int tx = threadIdx.x & 31, ty0 = threadIdx.x >> 5;
    #pragma unroll
    for (int r = 0; r < 4; r++) {
        int ty = ty0 + r*8;
        t[ty][tx] = W[(size_t)(k0+ty)*DD + n0 + tx];
    }
    __syncthreads();
    #pragma unroll
    for (int r = 0; r < 4; r++) {
        int ty = ty0 + r*8;
        float v = t[tx][ty];
        __nv_bfloat16 h = __float2bfloat16(v);
        Th[(size_t)(n0+ty)*DD + k0+tx] = h;
        Tl[(size_t)(n0+ty)*DD + k0+tx] = __float2bfloat16(v - __bfloat162float(h));
    }
}

// ---------------- fused depthwise conv ----------------
__global__ __launch_bounds__(256) void conv_all_kernel(
    const float* __restrict__ wq, const float* __restrict__ bq,
    const float* __restrict__ wk, const float* __restrict__ bk,
    const float* __restrict__ wv, const float* __restrict__ bv)
{
    __shared__ float red[8];
    int which = blockIdx.y;
    const float* P    = (which==0) ? g_qp : (which==1) ? g_kp : g_vp;
    float*       outp = (which==0) ? g_q  : (which==1) ? g_k  : g_v;
    const float* w    = (which==0) ? wq : (which==1) ? wk : wv;
    const float* bias = (which==0) ? bq : (which==1) ? bk : bv;
    int do_norm = (which < 2);
    int bid = blockIdx.x;
    int h = bid & 3; int bl = bid >> 2;
    int b = bl / LL, l = bl % LL;
    int ch = h*DKV + threadIdx.x;
    float4 wvv = *(const float4*)(w + (size_t)ch*4);
    const float wj[4] = {wvv.x, wvv.y, wvv.z, wvv.w};
    float val = bias[ch];
    #pragma unroll
    for (int j=0;j<4;j++) {
        int lp = l + j - 2;
        float xv = (lp>=0 && lp<LL) ? P[((size_t)b*LL+lp)*DD + ch] : 0.f;
        val += wj[j]*xv;
    }
    val = val * sigmoidf_(val);
    if (do_norm) {
        float s = warp_sum(val*val);
        if ((threadIdx.x & 31) == 0) red[threadIdx.x >> 5] = s;
        __syncthreads();
        if (threadIdx.x < 32) {
            float t = (threadIdx.x < 8) ? red[threadIdx.x] : 0.f;
            #pragma unroll
            for (int m = 4; m > 0; m >>= 1) t += __shfl_xor_sync(0xffffffffu, t, m);
            if (threadIdx.x == 0) red[0] = t;
        }
        __syncthreads();
        val = val / fmaxf(sqrtf(red[0]), 1e-6f);
    }
    outp[((size_t)b*LL+l)*DD + ch] = val;
}

// ---------------- smallproj + x hi/lo split fused ----------------
__global__ __launch_bounds__(256) void smallproj_kernel(
    const float* __restrict__ x,
    const float* __restrict__ Wb, const float* __restrict__ Wfd,
    const float* __restrict__ bfd, const float* __restrict__ fd_bias,
    const float* __restrict__ Wsd, const float* __restrict__ bsd, const float* __restrict__ sd_bias,
    const float* __restrict__ Wfg, const float* __restrict__ Wsg)
{
    __shared__ float red[8][20];
    int bl = blockIdx.x;
    int tid = threadIdx.x;
    int d0 = tid * 4;
    float4 xv = *(const float4*)&x[(size_t)bl*DD + d0];
    // split x -> bf16 hi/lo
    {
        __nv_bfloat16 h0 = __float2bfloat16(xv.x), h1 = __float2bfloat16(xv.y),
                      h2 = __float2bfloat16(xv.z), h3 = __float2bfloat16(xv.w);
        __nv_bfloat162* H2 = (__nv_bfloat162*)&g_xh[(size_t)bl*DD + d0];
        __nv_bfloat162* L2 = (__nv_bfloat162*)&g_xl[(size_t)bl*DD + d0];
        H2[0] = __nv_bfloat162(h0, h1);
        H2[1] = __nv_bfloat162(h2, h3);
        L2[0] = __nv_bfloat162(__float2bfloat16(xv.x - __bfloat162float(h0)),
                               __float2bfloat16(xv.y - __bfloat162float(h1)));
        L2[1] = __nv_bfloat162(__float2bfloat16(xv.z - __bfloat162float(h2)),
                               __float2bfloat16(xv.w - __bfloat162float(h3)));
    }
    float acc[20];
    #pragma unroll
    for (int j=0;j<20;j++) acc[j]=0.f;
    float xs[4] = {xv.x, xv.y, xv.z, xv.w};
    #pragma unroll
    for (int e=0;e<4;e++) {
        int d = d0 + e;
        #pragma unroll
        for (int h=0; h<4; h++) {
            acc[0*4+h] += xs[e] * Wb [d*4+h];
            acc[1*4+h] += xs[e] * Wfd[d*4+h];
            acc[2*4+h] += xs[e] * Wsd[d*4+h];
            acc[3*4+h] += xs[e] * Wfg[d*4+h];
            acc[4*4+h] += xs[e] * Wsg[d*4+h];
        }
    }
    #pragma unroll
    for (int j=0;j<20;j++) {
        float s = warp_sum(acc[j]);
        if ((tid & 31) == 0) red[tid >> 5][j] = s;
    }
    __syncthreads();
    if (tid < 20) {
        float s = 0.f;
        #pragma unroll
        for (int w = 0; w < 8; w++) s += red[w][tid];
        int p = tid/4, h = tid%4;
        int b = bl / LL, l = bl % LL;
        size_t oi = ((size_t)(b*HH + h))*LL + l;
        if      (p==0) g_beta[oi] = sigmoidf_(s);
        else if (p==1) g_fd[oi]   = sigmoidf_(s + bfd[h] + fd_bias[h]);
        else if (p==2) g_sd[oi]   = sigmoidf_(s + bsd[h] + sd_bias[h]);
        else if (p==3) g_gF[oi]   = sigmoidf_(s);
        else           g_gS[oi]   = sigmoidf_(s);
    }
}

// ---------------- psi (R12) ----------------
__global__ __launch_bounds__(256) void psi_kernel(
    const float* __restrict__ W_bil, const float* __restrict__ temp,
    const float* __restrict__ fw1, const float* __restrict__ fb1,
    const float* __restrict__ fw2, const float* __restrict__ fb2)
{
    extern __shared__ float sm[];
    float* kcs  = sm;
    float* us   = sm + 16384;
    float* flux = sm + 32768;
    float* red  = sm + 32768 + 520;
    int bhn = blockIdx.x;
    int n = bhn % NCH; int bh = bhn / NCH; int b = bh / HH, h = bh % HH;
    int tid = threadIdx.x;
    int l0 = n*CC;
    for (int i = tid; i < CC*DKV; i += 256) {
        int c = i >> 8, d = i & 255;
        size_t gi = ((size_t)b*LL + l0 + c)*DD + h*DKV + d;
        float bta = g_beta[(size_t)bh*LL + l0 + c];
        kcs[i] = g_k[gi];
        us[i]  = g_v[gi] * bta;
    }
    __syncthreads();
    int d = tid;
    float km=0.f, um=0.f;
    for (int c=0;c<CC;c++){ km += kcs[c*256+d]; um += us[c*256+d]; }
    flux[d]     = km * (1.f/CC);
    flux[256+d] = um * (1.f/CC);
    const float* W = W_bil + (size_t)h*DKV*DKV;
    float bsum = 0.f;
    for (int c0 = 0; c0 < CC; c0 += 16) {
        float dot[16];
        #pragma unroll
        for (int c2=0;c2<16;c2++) dot[c2]=0.f;
        for (int k4 = 0; k4 < 64; k4++) {
            float wv0 = W[(size_t)(k4*4+0)*DKV + d];
            float wv1 = W[(size_t)(k4*4+1)*DKV + d];
            float wv2 = W[(size_t)(k4*4+2)*DKV + d];
            float wv3 = W[(size_t)(k4*4+3)*DKV + d];
            #pragma unroll
            for (int c2=0;c2<16;c2++){
                float4 kc = *(float4*)&kcs[(c0+c2)*256 + k4*4];
                dot[c2] += kc.x*wv0 + kc.y*wv1 + kc.z*wv2 + kc.w*wv3;
            }
        }
        #pragma unroll
        for (int c2=0;c2<16;c2++) bsum += dot[c2] * us[(c0+c2)*256 + d];
    }
    red[tid] = bsum; __syncthreads();
    for (int s=128;s>0;s>>=1){ if(tid<s) red[tid]+=red[tid+s]; __syncthreads(); }
    if (tid==0) flux[512] = red[0] / (temp[h] * (float)CC);
    __syncthreads();
    float hj = 0.f;
    if (tid < 128) {
        float a = fb1[tid];
        for (int i=0;i<513;i++) a += flux[i]*fw1[i*128+tid];
        a = a * sigmoidf_(a);
        hj = a * fw2[tid];
    }
    red[tid] = hj; __syncthreads();
    for (int s=128;s>0;s>>=1){ if(tid<s) red[tid]+=red[tid+s]; __syncthreads(); }
    if (tid == 0) {
        float p = sigmoidf_(red[0] + fb2[0]);
        g_psi[bhn] = fminf(fmaxf(p, 0.01f), 0.99f);
    }
    __syncthreads();
    red[tid] = (tid<CC) ? logf(g_fd[(size_t)bh*LL + l0 + tid]) : 0.f;
    __syncthreads();
    for (int s=128;s>0;s>>=1){ if(tid<s) red[tid]+=red[tid+s]; __syncthreads(); }
    if (tid==0) g_gfc[bhn] = expf(red[0]);
    __syncthreads();
    red[tid] = (tid<CC) ? logf(g_sd[(size_t)bh*LL + l0 + tid]) : 0.f;
    __syncthreads();
    for (int s=128;s>0;s>>=1){ if(tid<s) red[tid]+=red[tid+s]; __syncthreads(); }
    if (tid==0) g_gsc[bhn] = expf(red[0]);
}

// ---------------- tfactor v4 (R14): 512 threads, concurrent Tu/Tw solves ----------------
__global__ __launch_bounds__(512) void tfactor_kernel()
{
    extern __shared__ float sm[];
    float* kT    = sm;                      // [256][68]
    float* As    = sm + 256*68;             // [64][68]
    float* ucl   = As + 64*68;              // [2][256][68]
    float* betas = ucl + 2*256*68;          // [64]
    int bhn = blockIdx.x;
    int n = bhn % NCH, bh = bhn/NCH, b = bh/HH, h = bh%HH;
    int l0 = n*CC, tid = threadIdx.x;
    int tc2 = tid >> 4, td = tid & 15;

    for (int i = tid; i < CC*DKV; i += 512) {
        int c = i >> 8, dk = i & 255;
        kT[dk*68 + c] = g_k[((size_t)b*LL + l0 + c)*DD + h*DKV + dk];
    }
    if (tid < CC) betas[tid] = g_beta[(size_t)bh*LL + l0 + tid];
    __syncthreads();
    {
        float a2[2][4];
        #pragma unroll
        for (int i=0;i<2;i++)
            #pragma unroll
            for (int j=0;j<4;j++) a2[i][j]=0.f;
        for (int k=0;k<DKV;k++){
            float av[2], bv[4];
            #pragma unroll
            for (int i=0;i<2;i++) av[i] = kT[k*68 + tc2*2+i];
            #pragma unroll
            for (int j=0;j<4;j++) bv[j] = kT[k*68 + td*4+j];
            #pragma unroll
            for (int i=0;i<2;i++)
                #pragma unroll
                for (int j=0;j<4;j++) a2[i][j] += av[i]*bv[j];
        }
        #pragma unroll
        for (int i=0;i<2;i++)
            #pragma unroll
            for (int j=0;j<4;j++){
                int c = tc2*2+i, dc = td*4+j;
                As[c*68+dc] = (dc < c) ? betas[c]*a2[i][j] : 0.f;
            }
    }
    __syncthreads();
    {
        int half = tid >> 8;
        int d = tid & 255;
        float* uc = &ucl[half*256*68 + d*68];
        if (half == 0) {
            const float* vb = g_v + ((size_t)b*LL+l0)*DD + h*DKV + d;
            for (int c=0;c<CC;c++) uc[c] = vb[(size_t)c*DD] * betas[c];
        } else {
            for (int c=0;c<CC;c++) uc[c] = betas[c]*kT[d*68+c];
        }
        for (int c=1;c<CC;c++){
            const float* Ar = &As[c*68];
            float s = 0.f;
            int cq = c >> 2;
            for (int mq=0; mq<cq; mq++){
                float4 a = *(float4*)&Ar[mq*4];
                float4 u = *(float4*)&uc[mq*4];
                s += a.x*u.x + a.y*u.y + a.z*u.z + a.w*u.w;
            }
            for (int m=cq*4; m<c; m++) s += Ar[m]*uc[m];
            uc[c] -= s;
        }
        float* dst = (half == 0) ? g_Tu : g_Tw;
        for (int c=0;c<CC;c++) dst[((size_t)bhn*CC + c)*DKV + d] = uc[c];
    }
    __syncthreads();
    {
        float t2[2][4];
        #pragma unroll
        for (int i=0;i<2;i++)
            #pragma unroll
            for (int j=0;j<4;j++) t2[i][j]=0.f;
        for (int ks=0; ks<4; ks++){
            __syncthreads();
            for (int i = tid; i < CC*64; i += 512){
                int c = i>>6, kk = i&63;
                As[c*68+kk] = g_q[((size_t)b*LL+l0+c)*DD + h*DKV + ks*64+kk];
            }
            __syncthreads();
            for (int kk=0;kk<64;kk++){
                int k = ks*64+kk;
                float av[2], bv[4];
                #pragma unroll
                for (int i=0;i<2;i++) av[i] = As[(tc2*2+i)*68 + kk];
                #pragma unroll
                for (int j=0;j<4;j++) bv[j] = kT[k*68 + td*4+j];
                #pragma unroll
                for (int i=0;i<2;i++)
                    #pragma unroll
                    for (int j=0;j<4;j++) t2[i][j] += av[i]*bv[j];
            }
        }
        #pragma unroll
        for (int i=0;i<2;i++)
            #pragma unroll
            for (int j=0;j<4;j++){
                int c = tc2*2+i, dc = td*4+j;
                g_attn[(size_t)bhn*CC*CC + c*CC + dc] = (dc <= c) ? t2[i][j] : 0.f;
            }
    }
}

// ---------------- scan v5: 512 threads, full-chunk staging, 4 barriers/chunk ----------------
#define ACC2(Cm) { float s0=sf0.Cm+ss0.Cm, s1=sf1.Cm+ss1.Cm;         \
    au0 -= tw.Cm*s0; au1 -= tw.Cm*s1;                                \
    af0 += q.Cm*sf0.Cm; af1 += q.Cm*sf1.Cm;                          \
    as0 += q.Cm*ss0.Cm; as1 += q.Cm*ss1.Cm; }

__global__ __launch_bounds__(512) void scan_kernel()
{
    extern __shared__ float sm[];
    float* SfT = sm;                    // [16][260]
    float* SsT = SfT + 16*SP;           // [16][260]
    float* TwS = SsT + 16*SP;           // [64][260]  (also k)
    float* QS  = TwS + 64*SP;           // [64][260]  (also attn, stride 68)
    float* Uc  = QS + 64*SP;            // [64][20]
    int tid = threadIdx.x;
    int bh = blockIdx.x / CT, tile = blockIdx.x % CT;
    int b = bh / HH, h = bh % HH;
    int col0 = tile * TV;
    int rA = tid >> 3;                  // c row (phase A / o_intra)
    int cA = (tid & 7) * 2;             // v pair
    int kth = tid >> 1;                 // kU: k (0..255)
    int vh  = (tid & 1) * 8;            // kU: v half (8 values)
    for (int i = tid; i < 16*SP; i += 512) { SfT[i]=0.f; SsT[i]=0.f; }
    __syncthreads();
    const float* qg = g_q + (size_t)b*LL*DD + h*DKV;
    const float* kg = g_k + (size_t)b*LL*DD + h*DKV;
    for (int n = 0; n < NCH; n++) {
        int bhn = bh*NCH + n;
        float psi = g_psi[bhn], gf = g_gfc[bhn], gs = g_gsc[bhn];
        size_t tbase = (size_t)bhn*CC*DKV;
        // ---- stage full Tw + q for the chunk
        for (int i = tid; i < 4096; i += 512) {
            int c = i >> 6, kq = (i & 63) * 4;
            *(float4*)&TwS[c*SP+kq] = *(const float4*)&g_Tw[tbase + (size_t)c*DKV + kq];
            *(float4*)&QS [c*SP+kq] = *(const float4*)&qg[(size_t)(n*CC+c)*DD + kq];
        }
        __syncthreads();
        // ---- phase A: full k range
        float au0=0,au1=0, af0=0,af1=0, as0=0,as1=0;
        #pragma unroll 4
        for (int k4 = 0; k4 < 64; k4++) {
            int kk = k4*4;
            float4 sf0 = *(float4*)&SfT[cA*SP + kk];
            float4 sf1 = *(float4*)&SfT[(cA+1)*SP + kk];
            float4 ss0 = *(float4*)&SsT[cA*SP + kk];
            float4 ss1 = *(float4*)&SsT[(cA+1)*SP + kk];
            float4 tw  = *(float4*)&TwS[rA*SP + kk];
            float4 q   = *(float4*)&QS[rA*SP + kk];
            ACC2(x) ACC2(y) ACC2(z) ACC2(w)
        }
        // u_corr
        {
            float t0 = g_Tu[tbase + (size_t)rA*DKV + col0+cA]   + au0;
            float t1 = g_Tu[tbase + (size_t)rA*DKV + col0+cA+1] + au1;
            Uc[rA*20 + cA]   = t0;
            Uc[rA*20 + cA+1] = t1;
        }
        __syncthreads();
        // ---- restage: attn into QS (stride 68), k into TwS (full)
        for (int i = tid; i < 1024; i += 512) {
            int c = i >> 4, kq = (i & 15) * 4;
            *(float4*)&QS[c*68+kq] = *(const float4*)&g_attn[(size_t)bhn*CC*CC + c*CC + kq];
        }
        for (int i = tid; i < 4096; i += 512) {
            int c = i >> 6, kq = (i & 63) * 4;
            *(float4*)&TwS[c*SP+kq] = *(const float4*)&kg[(size_t)(n*CC+c)*DD + kq];
        }
        __syncthreads();
        // ---- o_intra + output
        {
            float oi0=0, oi1=0;
            #pragma unroll 4
            for (int dq = 0; dq < 16; dq++) {
                float4 a = *(float4*)&QS[rA*68 + dq*4];
                float2 u0 = *(float2*)&Uc[(dq*4+0)*20 + cA];
                float2 u1 = *(float2*)&Uc[(dq*4+1)*20 + cA];
                float2 u2 = *(float2*)&Uc[(dq*4+2)*20 + cA];
                float2 u3 = *(float2*)&Uc[(dq*4+3)*20 + cA];
                oi0 += a.x*u0.x + a.y*u1.x + a.z*u2.x + a.w*u3.x;
                oi1 += a.x*u0.y + a.y*u1.y + a.z*u2.y + a.w*u3.y;
            }
            int l = n*CC + rA;
            float gFv = g_gF[(size_t)bh*LL + l];
            float gSv = g_gS[(size_t)bh*LL + l];
            *(float2*)&g_o[((size_t)bh*LL + l)*DKV + col0 + cA] =
                make_float2(gFv*af0 + gSv*as0 + oi0, gFv*af1 + gSv*as1 + oi1);
        }
        // ---- kU + state update: thread = (k = kth, v in [vh, vh+8))
        {
            float psn = 1.f - psi;
            float ku[8];
            #pragma unroll
            for (int e=0;e<8;e++) ku[e]=0.f;
            #pragma unroll 8
            for (int c = 0; c < CC; c++) {
                float kv = TwS[c*SP + kth];
                float4 ua = *(float4*)&Uc[c*20 + vh];
                float4 ub = *(float4*)&Uc[c*20 + vh + 4];
                ku[0]+=kv*ua.x; ku[1]+=kv*ua.y; ku[2]+=kv*ua.z; ku[3]+=kv*ua.w;
                ku[4]+=kv*ub.x; ku[5]+=kv*ub.y; ku[6]+=kv*ub.z; ku[7]+=kv*ub.w;
            }
            #pragma unroll
            for (int e=0;e<8;e++) {
                int idx = (vh+e)*SP + kth;
                SfT[idx] = gf*SfT[idx] + psn*ku[e];
                SsT[idx] = gs*SsT[idx] + psi*ku[e];
            }
        }
        __syncthreads();
    }
}

// ---------------- gated RMSNorm + bf16 hi/lo split fused ----------------
__global__ __launch_bounds__(256) void onorm_kernel(
    const float* __restrict__ onw)
{
    __shared__ float red[8];
    int bid = blockIdx.x;
    int h = bid & 3; int bl = bid >> 2;
    int b = bl / LL, l = bl % LL;
    int v = threadIdx.x;
    float val = g_o[(((size_t)(b*HH+h))*LL + l)*DKV + v];
    float s = warp_sum(val*val);
    if ((v & 31) == 0) red[v >> 5] = s;
    __syncthreads();
    if (v < 32) {
        float t = (v < 8) ? red[v] : 0.f;
        #pragma unroll
        for (int m = 4; m > 0; m >>= 1) t += __shfl_xor_sync(0xffffffffu, t, m);
        if (v == 0) red[0] = t;
    }
    __syncthreads();
    float scale = rsqrtf(red[0]*(1.f/DKV) + 1e-5f);
    float gv = g_gp[(size_t)bl*DD + h*DKV + v];
    float out = val*scale*onw[v]*sigmoidf_(gv);
    __nv_bfloat16 hi = __float2bfloat16(out);
    size_t oi = (size_t)bl*DD + h*DKV + v;
    g_onh[oi] = hi;
    g_onl[oi] = __float2bfloat16(out - __bfloat162float(hi));
}

// ---------------- launch ----------------
extern "C" void kernel_launch(void* const* d_in, const int* in_sizes, int n_in,
                              void* d_out, int out_size)
{
    const float* x     = (const float*)d_in[0];
    const float* Wq    = (const float*)d_in[1];
    const float* Wk    = (const float*)d_in[2];
    const float* Wv    = (const float*)d_in[3];
    const float* cq_w  = (const float*)d_in[4];
    const float* cq_b  = (const float*)d_in[5];
    const float* ck_w  = (const float*)d_in[6];
    const float* ck_b  = (const float*)d_in[7];
    const float* cv_w  = (const float*)d_in[8];
    const float* cv_b  = (const float*)d_in[9];
    const float* Wb    = (const float*)d_in[10];
    const float* Wfd   = (const float*)d_in[11];
    const float* bfd   = (const float*)d_in[12];
    const float* fdb   = (const float*)d_in[13];
    const float* Wsd   = (const float*)d_in[14];
    const float* bsd   = (const float*)d_in[15];
    const float* sdb   = (const float*)d_in[16];
    const float* W_bil = (const float*)d_in[17];
    const float* temp  = (const float*)d_in[18];
    const float* fw1   = (const float*)d_in[19];
    const float* fb1   = (const float*)d_in[20];
    const float* fw2   = (const float*)d_in[21];
    const float* fb2   = (const float*)d_in[22];
    const float* Wfg   = (const float*)d_in[23];
    const float* Wsg   = (const float*)d_in[24];
    const float* Wg    = (const float*)d_in[25];
    const float* onw   = (const float*)d_in[26];
    const float* Wo    = (const float*)d_in[27];
    float* out = (float*)d_out;

    __nv_bfloat16 *p_xh,*p_xl,*p_onh,*p_onl;
    cudaGetSymbolAddress((void**)&p_xh, g_xh);
    cudaGetSymbolAddress((void**)&p_xl, g_xl);
    cudaGetSymbolAddress((void**)&p_onh, g_onh);
    cudaGetSymbolAddress((void**)&p_onl, g_onl);

    int psi_smem  = (16384+16384+520+256)*4;
    int tf_smem   = (256*68 + 64*68 + 2*256*68 + 64)*4;
    int scan_smem = (2*16*SP + 2*64*SP + 64*20)*4;
    cudaFuncSetAttribute(psi_kernel,      cudaFuncAttributeMaxDynamicSharedMemorySize, psi_smem);
    cudaFuncSetAttribute(tfactor_kernel,  cudaFuncAttributeMaxDynamicSharedMemorySize, tf_smem);
    cudaFuncSetAttribute(scan_kernel,     cudaFuncAttributeMaxDynamicSharedMemorySize, scan_smem);
    cudaFuncSetAttribute(gemm_proj_kernel, cudaFuncAttributeMaxDynamicSharedMemorySize, GEMM_SMEM);
    cudaFuncSetAttribute(gemm_wo_kernel,   cudaFuncAttributeMaxDynamicSharedMemorySize, GEMM_SMEM);

    // smallproj also produces xh/xl -> must precede GEMMs
    smallproj_kernel<<<BLD, 256>>>(x, Wb, Wfd, bfd, fdb, Wsd, bsd, sdb, Wfg, Wsg);
    dim3 wtg(DD/32, DD/32, 5);
    wtrans_all_kernel<<<wtg, 256>>>(Wq, Wk, Wv, Wg, Wo);
    dim3 gp(GN/128, BLD/128, 4);
    gemm_proj_kernel<<<gp, 256, GEMM_SMEM>>>(p_xh, p_xl);
    dim3 cg(BLD*HH, 3);
    conv_all_kernel<<<cg, 256>>>(cq_w, cq_b, ck_w, ck_b, cv_w, cv_b);
    tfactor_kernel<<<BH*NCH, 512, tf_smem>>>();
    psi_kernel<<<BH*NCH, 256, psi_smem>>>(W_bil, temp, fw1, fb1, fw2, fb2);
    scan_kernel<<<BH*CT, 512, scan_smem>>>();
    onorm_kernel<<<BLD*HH, 256>>>(onw);
    dim3 gw(GN/128, BLD/128);
    gemm_wo_kernel<<<gw, 256, GEMM_SMEM>>>(p_onh, p_onl, out);
}

// round 16
// speedup vs baseline: 1.3085x; 1.1790x over previous
#include <cuda_runtime.h>
#include <cuda_bf16.h>
#include <math.h>
#include <stdint.h>

#define BB   2
#define LL   4096
#define DD   1024
#define HH   4
#define DKV  256
#define CC   64
#define NCH  64
#define BH   (BB*HH)
#define BLD  (BB*LL)
#define CT   16
#define TV   16
#define WSZ  ((size_t)DD*DD)
#define SP   260

// ---------------- scratch ----------------
__device__ float g_qp[BLD*DD];
__device__ float g_kp[BLD*DD];
__device__ float g_vp[BLD*DD];
__device__ float g_q [BLD*DD];
__device__ float g_k [BLD*DD];
__device__ float g_v [BLD*DD];
__device__ float g_gp[BLD*DD];
__device__ float g_beta[BH*LL];
__device__ float g_fd[BH*LL];
__device__ float g_sd[BH*LL];
__device__ float g_gF[BH*LL];
__device__ float g_gS[BH*LL];
__device__ float g_psi[BH*NCH];
__device__ float g_gfc[BH*NCH];
__device__ float g_gsc[BH*NCH];
__device__ float g_Tu[(size_t)BH*NCH*CC*DKV];
__device__ float g_Tw[(size_t)BH*NCH*CC*DKV];
__device__ float g_attn[(size_t)BH*NCH*CC*CC];
__device__ float g_o [(size_t)BH*LL*DKV];

__device__ __nv_bfloat16 g_xh[(size_t)BLD*DD];
__device__ __nv_bfloat16 g_xl[(size_t)BLD*DD];
__device__ __nv_bfloat16 g_onh[(size_t)BLD*DD];
__device__ __nv_bfloat16 g_onl[(size_t)BLD*DD];
__device__ __nv_bfloat16 g_wth[(size_t)5*DD*DD];
__device__ __nv_bfloat16 g_wtl[(size_t)5*DD*DD];

__device__ __forceinline__ float sigmoidf_(float x){ return 1.f/(1.f+expf(-x)); }
__device__ __forceinline__ float warp_sum(float v){
    #pragma unroll
    for (int m = 16; m > 0; m >>= 1) v += __shfl_xor_sync(0xffffffffu, v, m);
    return v;
}
#define CP_ASYNC16(smaddr, gptr) \
    asm volatile("cp.async.ca.shared.global [%0], [%1], 16;" :: "r"(smaddr), "l"(gptr) : "memory")
#define CP_COMMIT() asm volatile("cp.async.commit_group;" ::: "memory")
#define CP_WAIT0()  asm volatile("cp.async.wait_group 0;" ::: "memory")

// ================= mma.sync split-bf16 GEMM, cp.async double-buffered (R12) =================
#define GK   1024
#define GN   1024
#define SAST 40
#define GBUF (4*128*SAST)
#define GEMM_SMEM (2*GBUF*2)

#define MMA16816(d, a0, a1, a2, a3, b0, b1)                                   \
    asm volatile("mma.sync.aligned.m16n8k16.row.col.f32.bf16.bf16.f32 "       \
        "{%0,%1,%2,%3}, {%4,%5,%6,%7}, {%8,%9}, {%0,%1,%2,%3};"               \
        : "+f"(d[0]), "+f"(d[1]), "+f"(d[2]), "+f"(d[3])                      \
        : "r"(a0), "r"(a1), "r"(a2), "r"(a3), "r"(b0), "r"(b1))

__device__ __forceinline__ void gemm_fill_async(
    __nv_bfloat16* buf, uint32_t buf_sa,
    const __nv_bfloat16* Ah, const __nv_bfloat16* Al,
    const __nv_bfloat16* Bh, const __nv_bfloat16* Bl,
    int m0, int n0, int k0, int tid)
{
    #pragma unroll
    for (int it = 0; it < 2; it++) {
        int i = tid + it*256;
        int r = i >> 2, c = (i & 3) * 8;
        size_t ga = (size_t)(m0 + r)*GK + k0 + c;
        size_t gb = (size_t)(n0 + r)*GK + k0 + c;
        uint32_t so = (uint32_t)((r*SAST + c) * 2);
        CP_ASYNC16(buf_sa + 0*128*SAST*2 + so, Ah + ga);
        CP_ASYNC16(buf_sa + 1*128*SAST*2 + so, Al + ga);
        CP_ASYNC16(buf_sa + 2*128*SAST*2 + so, Bh + gb);
        CP_ASYNC16(buf_sa + 3*128*SAST*2 + so, Bl + gb);
    }
}

__device__ __forceinline__ void gemm_body(
    const __nv_bfloat16* __restrict__ Ah, const __nv_bfloat16* __restrict__ Al,
    const __nv_bfloat16* __restrict__ Bh, const __nv_bfloat16* __restrict__ Bl,
    float* __restrict__ C, __nv_bfloat16* smbase)
{
    int tid = threadIdx.x;
    int warp = tid >> 5, lane = tid & 31;
    int wm = warp >> 1, wn = warp & 1;
    int m0 = blockIdx.y * 128, n0 = blockIdx.x * 128;
    int lg = lane >> 2;
    int lt = lane & 3;
    uint32_t smb_sa = (uint32_t)__cvta_generic_to_shared(smbase);

    float acc[2][8][4];
    #pragma unroll
    for (int mi=0; mi<2; mi++)
        #pragma unroll
        for (int ni=0; ni<8; ni++)
            #pragma unroll
            for (int r=0; r<4; r++) acc[mi][ni][r] = 0.f;

    gemm_fill_async(smbase, smb_sa, Ah, Al, Bh, Bl, m0, n0, 0, tid);
    CP_COMMIT();

    for (int t = 0; t < GK/32; t++) {
        CP_WAIT0();
        __syncthreads();
        __nv_bfloat16* buf = smbase + (t & 1)*GBUF;
        if (t + 1 < GK/32) {
            gemm_fill_async(smbase, smb_sa + ((t+1)&1)*GBUF*2,
                            Ah, Al, Bh, Bl, m0, n0, (t+1)*32, tid);
            CP_COMMIT();
        }
        __nv_bfloat16* sAh = buf;
        __nv_bfloat16* sAl = buf + 128*SAST;
        __nv_bfloat16* sBh = buf + 2*128*SAST;
        __nv_bfloat16* sBl = buf + 3*128*SAST;
        #pragma unroll
        for (int ks = 0; ks < 2; ks++) {
            int kb = ks*16 + lt*2;
            uint32_t aH[2][4], aL[2][4];
            #pragma unroll
            for (int mi = 0; mi < 2; mi++) {
                int row = wm*32 + mi*16 + lg;
                aH[mi][0] = *(uint32_t*)&sAh[row*SAST + kb];
                aH[mi][1] = *(uint32_t*)&sAh[(row+8)*SAST + kb];
                aH[mi][2] = *(uint32_t*)&sAh[row*SAST + kb + 8];
                aH[mi][3] = *(uint32_t*)&sAh[(row+8)*SAST + kb + 8];
                aL[mi][0] = *(uint32_t*)&sAl[row*SAST + kb];
                aL[mi][1] = *(uint32_t*)&sAl[(row+8)*SAST + kb];
                aL[mi][2] = *(uint32_t*)&sAl[row*SAST + kb + 8];
                aL[mi][3] = *(uint32_t*)&sAl[(row+8)*SAST + kb + 8];
            }
            #pragma unroll
            for (int ni = 0; ni < 8; ni++) {
                int nr = wn*64 + ni*8 + lg;
                uint32_t bh0 = *(uint32_t*)&sBh[nr*SAST + kb];
                uint32_t bh1 = *(uint32_t*)&sBh[nr*SAST + kb + 8];
                uint32_t bl0 = *(uint32_t*)&sBl[nr*SAST + kb];
                uint32_t bl1 = *(uint32_t*)&sBl[nr*SAST + kb + 8];
                #pragma unroll
                for (int mi = 0; mi < 2; mi++) {
                    MMA16816(acc[mi][ni], aH[mi][0],aH[mi][1],aH[mi][2],aH[mi][3], bh0, bh1);
                    MMA16816(acc[mi][ni], aH[mi][0],aH[mi][1],aH[mi][2],aH[mi][3], bl0, bl1);
                    MMA16816(acc[mi][ni], aL[mi][0],aL[mi][1],aL[mi][2],aL[mi][3], bh0, bh1);
                }
            }
        }
        __syncthreads();
    }
    #pragma unroll
    for (int mi = 0; mi < 2; mi++) {
        int row = m0 + wm*32 + mi*16 + lg;
        #pragma unroll
        for (int ni = 0; ni < 8; ni++) {
            int col = n0 + wn*64 + ni*8 + lt*2;
            *(float2*)&C[(size_t)row*GN + col]     = make_float2(acc[mi][ni][0], acc[mi][ni][1]);
            *(float2*)&C[(size_t)(row+8)*GN + col] = make_float2(acc[mi][ni][2], acc[mi][ni][3]);
        }
    }
}

__global__ __launch_bounds__(256, 2) void gemm_proj_kernel(
    const __nv_bfloat16* __restrict__ Ah, const __nv_bfloat16* __restrict__ Al)
{
    extern __shared__ float sm[];
    int z = blockIdx.z;
    float* C = (z==0) ? g_qp : (z==1) ? g_kp : (z==2) ? g_vp : g_gp;
    gemm_body(Ah, Al, g_wth + (size_t)z*WSZ, g_wtl + (size_t)z*WSZ, C, (__nv_bfloat16*)sm);
}

__global__ __launch_bounds__(256, 2) void gemm_wo_kernel(
    const __nv_bfloat16* __restrict__ Ah, const __nv_bfloat16* __restrict__ Al,
    float* __restrict__ C)
{
    extern __shared__ float sm[];
    gemm_body(Ah, Al, g_wth + 4*WSZ, g_wtl + 4*WSZ, C, (__nv_bfloat16*)sm);
}

// ---------------- fused weight transpose+split ----------------
__global__ __launch_bounds__(256) void wtrans_all_kernel(
    const float* __restrict__ W0, const float* __restrict__ W1,
    const float* __restrict__ W2, const float* __restrict__ W3,
    const float* __restrict__ W4)
{
    __shared__ float t[32][33];
    int z = blockIdx.z;
    const float* W = (z==0)?W0 : (z==1)?W1 : (z==2)?W2 : (z==3)?W3 : W4;
    __nv_bfloat16* Th = g_wth + (size_t)z*WSZ;
    __nv_bfloat16* Tl = g_wtl + (size_t)z*WSZ;
    int n0 = blockIdx.x*32, k0 = blockIdx.y*32;
    int tx = threadIdx.x & 31, ty0 = threadIdx.x >> 5;
    #pragma unroll
    for (int r = 0; r < 4; r++) {
        int ty = ty0 + r*8;
        t[ty][tx] = W[(size_t)(k0+ty)*DD + n0 + tx];
    }
    __syncthreads();
    #pragma unroll
    for (int r = 0; r < 4; r++) {
        int ty = ty0 + r*8;
        float v = t[tx][ty];
        __nv_bfloat16 h = __float2bfloat16(v);
        Th[(size_t)(n0+ty)*DD + k0+tx] = h;
        Tl[(size_t)(n0+ty)*DD + k0+tx] = __float2bfloat16(v - __bfloat162float(h));
    }
}

// ---------------- fused depthwise conv ----------------
__global__ __launch_bounds__(256) void conv_all_kernel(
    const float* __restrict__ wq, const float* __restrict__ bq,
    const float* __restrict__ wk, const float* __restrict__ bk,
    const float* __restrict__ wv, const float* __restrict__ bv)
{
    __shared__ float red[8];
    int which = blockIdx.y;
    const float* P    = (which==0) ? g_qp : (which==1) ? g_kp : g_vp;
    float*       outp = (which==0) ? g_q  : (which==1) ? g_k  : g_v;
    const float* w    = (which==0) ? wq : (which==1) ? wk : wv;
    const float* bias = (which==0) ? bq : (which==1) ? bk : bv;
    int do_norm = (which < 2);
    int bid = blockIdx.x;
    int h = bid & 3; int bl = bid >> 2;
    int b = bl / LL, l = bl % LL;
    int ch = h*DKV + threadIdx.x;
    float4 wvv = *(const float4*)(w + (size_t)ch*4);
    const float wj[4] = {wvv.x, wvv.y, wvv.z, wvv.w};
    float val = bias[ch];
    #pragma unroll
    for (int j=0;j<4;j++) {
        int lp = l + j - 2;
        float xv = (lp>=0 && lp<LL) ? P[((size_t)b*LL+lp)*DD + ch] : 0.f;
        val += wj[j]*xv;
    }
    val = val * sigmoidf_(val);
    if (do_norm) {
        float s = warp_sum(val*val);
        if ((threadIdx.x & 31) == 0) red[threadIdx.x >> 5] = s;
        __syncthreads();
        if (threadIdx.x < 32) {
            float t = (threadIdx.x < 8) ? red[threadIdx.x] : 0.f;
            #pragma unroll
            for (int m = 4; m > 0; m >>= 1) t += __shfl_xor_sync(0xffffffffu, t, m);
            if (threadIdx.x == 0) red[0] = t;
        }
        __syncthreads();
        val = val / fmaxf(sqrtf(red[0]), 1e-6f);
    }
    outp[((size_t)b*LL+l)*DD + ch] = val;
}

// ---------------- smallproj + x hi/lo split fused ----------------
__global__ __launch_bounds__(256) void smallproj_kernel(
    const float* __restrict__ x,
    const float* __restrict__ Wb, const float* __restrict__ Wfd,
    const float* __restrict__ bfd, const float* __restrict__ fd_bias,
    const float* __restrict__ Wsd, const float* __restrict__ bsd, const float* __restrict__ sd_bias,
    const float* __restrict__ Wfg, const float* __restrict__ Wsg)
{
    __shared__ float red[8][20];
    int bl = blockIdx.x;
    int tid = threadIdx.x;
    int d0 = tid * 4;
    float4 xv = *(const float4*)&x[(size_t)bl*DD + d0];
    {
        __nv_bfloat16 h0 = __float2bfloat16(xv.x), h1 = __float2bfloat16(xv.y),
                      h2 = __float2bfloat16(xv.z), h3 = __float2bfloat16(xv.w);
        __nv_bfloat162* H2 = (__nv_bfloat162*)&g_xh[(size_t)bl*DD + d0];
        __nv_bfloat162* L2 = (__nv_bfloat162*)&g_xl[(size_t)bl*DD + d0];
        H2[0] = __nv_bfloat162(h0, h1);
        H2[1] = __nv_bfloat162(h2, h3);
        L2[0] = __nv_bfloat162(__float2bfloat16(xv.x - __bfloat162float(h0)),
                               __float2bfloat16(xv.y - __bfloat162float(h1)));
        L2[1] = __nv_bfloat162(__float2bfloat16(xv.z - __bfloat162float(h2)),
                               __float2bfloat16(xv.w - __bfloat162float(h3)));
    }
    float acc[20];
    #pragma unroll
    for (int j=0;j<20;j++) acc[j]=0.f;
    float xs[4] = {xv.x, xv.y, xv.z, xv.w};
    #pragma unroll
    for (int e=0;e<4;e++) {
        int d = d0 + e;
        #pragma unroll
        for (int h=0; h<4; h++) {
            acc[0*4+h] += xs[e] * Wb [d*4+h];
            acc[1*4+h] += xs[e] * Wfd[d*4+h];
            acc[2*4+h] += xs[e] * Wsd[d*4+h];
            acc[3*4+h] += xs[e] * Wfg[d*4+h];
            acc[4*4+h] += xs[e] * Wsg[d*4+h];
        }
    }
    #pragma unroll
    for (int j=0;j<20;j++) {
        float s = warp_sum(acc[j]);
        if ((tid & 31) == 0) red[tid >> 5][j] = s;
    }
    __syncthreads();
    if (tid < 20) {
        float s = 0.f;
        #pragma unroll
        for (int w = 0; w < 8; w++) s += red[w][tid];
        int p = tid/4, h = tid%4;
        int b = bl / LL, l = bl % LL;
        size_t oi = ((size_t)(b*HH + h))*LL + l;
        if      (p==0) g_beta[oi] = sigmoidf_(s);
        else if (p==1) g_fd[oi]   = sigmoidf_(s + bfd[h] + fd_bias[h]);
        else if (p==2) g_sd[oi]   = sigmoidf_(s + bsd[h] + sd_bias[h]);
        else if (p==3) g_gF[oi]   = sigmoidf_(s);
        else           g_gS[oi]   = sigmoidf_(s);
    }
}

// ---------------- psi (R12) ----------------
__global__ __launch_bounds__(256) void psi_kernel(
    const float* __restrict__ W_bil, const float* __restrict__ temp,
    const float* __restrict__ fw1, const float* __restrict__ fb1,
    const float* __restrict__ fw2, const float* __restrict__ fb2)
{
    extern __shared__ float sm[];
    float* kcs  = sm;
    float* us   = sm + 16384;
    float* flux = sm + 32768;
    float* red  = sm + 32768 + 520;
    int bhn = blockIdx.x;
    int n = bhn % NCH; int bh = bhn / NCH; int b = bh / HH, h = bh % HH;
    int tid = threadIdx.x;
    int l0 = n*CC;
    for (int i = tid; i < CC*DKV; i += 256) {
        int c = i >> 8, d = i & 255;
        size_t gi = ((size_t)b*LL + l0 + c)*DD + h*DKV + d;
        float bta = g_beta[(size_t)bh*LL + l0 + c];
        kcs[i] = g_k[gi];
        us[i]  = g_v[gi] * bta;
    }
    __syncthreads();
    int d = tid;
    float km=0.f, um=0.f;
    for (int c=0;c<CC;c++){ km += kcs[c*256+d]; um += us[c*256+d]; }
    flux[d]     = km * (1.f/CC);
    flux[256+d] = um * (1.f/CC);
    const float* W = W_bil + (size_t)h*DKV*DKV;
    float bsum = 0.f;
    for (int c0 = 0; c0 < CC; c0 += 16) {
        float dot[16];
        #pragma unroll
        for (int c2=0;c2<16;c2++) dot[c2]=0.f;
        for (int k4 = 0; k4 < 64; k4++) {
            float wv0 = W[(size_t)(k4*4+0)*DKV + d];
            float wv1 = W[(size_t)(k4*4+1)*DKV + d];
            float wv2 = W[(size_t)(k4*4+2)*DKV + d];
            float wv3 = W[(size_t)(k4*4+3)*DKV + d];
            #pragma unroll
            for (int c2=0;c2<16;c2++){
                float4 kc = *(float4*)&kcs[(c0+c2)*256 + k4*4];
                dot[c2] += kc.x*wv0 + kc.y*wv1 + kc.z*wv2 + kc.w*wv3;
            }
        }
        #pragma unroll
        for (int c2=0;c2<16;c2++) bsum += dot[c2] * us[(c0+c2)*256 + d];
    }
    red[tid] = bsum; __syncthreads();
    for (int s=128;s>0;s>>=1){ if(tid<s) red[tid]+=red[tid+s]; __syncthreads(); }
    if (tid==0) flux[512] = red[0] / (temp[h] * (float)CC);
    __syncthreads();
    float hj = 0.f;
    if (tid < 128) {
        float a = fb1[tid];
        for (int i=0;i<513;i++) a += flux[i]*fw1[i*128+tid];
        a = a * sigmoidf_(a);
        hj = a * fw2[tid];
    }
    red[tid] = hj; __syncthreads();
    for (int s=128;s>0;s>>=1){ if(tid<s) red[tid]+=red[tid+s]; __syncthreads(); }
    if (tid == 0) {
        float p = sigmoidf_(red[0] + fb2[0]);
        g_psi[bhn] = fminf(fmaxf(p, 0.01f), 0.99f);
    }
    __syncthreads();
    red[tid] = (tid<CC) ? logf(g_fd[(size_t)bh*LL + l0 + tid]) : 0.f;
    __syncthreads();
    for (int s=128;s>0;s>>=1){ if(tid<s) red[tid]+=red[tid+s]; __syncthreads(); }
    if (tid==0) g_gfc[bhn] = expf(red[0]);
    __syncthreads();
    red[tid] = (tid<CC) ? logf(g_sd[(size_t)bh*LL + l0 + tid]) : 0.f;
    __syncthreads();
    for (int s=128;s>0;s>>=1){ if(tid<s) red[tid]+=red[tid+s]; __syncthreads(); }
    if (tid==0) g_gsc[bhn] = expf(red[0]);
}

// ---------------- tfactor v4 (R14) ----------------
__global__ __launch_bounds__(512) void tfactor_kernel()
{
    extern __shared__ float sm[];
    float* kT    = sm;                      // [256][68]
    float* As    = sm + 256*68;             // [64][68]
    float* ucl   = As + 64*68;              // [2][256][68]
    float* betas = ucl + 2*256*68;          // [64]
    int bhn = blockIdx.x;
    int n = bhn % NCH, bh = bhn/NCH, b = bh/HH, h = bh%HH;
    int l0 = n*CC, tid = threadIdx.x;
    int tc2 = tid >> 4, td = tid & 15;

    for (int i = tid; i < CC*DKV; i += 512) {
        int c = i >> 8, dk = i & 255;
        kT[dk*68 + c] = g_k[((size_t)b*LL + l0 + c)*DD + h*DKV + dk];
    }
    if (tid < CC) betas[tid] = g_beta[(size_t)bh*LL + l0 + tid];
    __syncthreads();
    {
        float a2[2][4];
        #pragma unroll
        for (int i=0;i<2;i++)
            #pragma unroll
            for (int j=0;j<4;j++) a2[i][j]=0.f;
        for (int k=0;k<DKV;k++){
            float av[2], bv[4];
            #pragma unroll
            for (int i=0;i<2;i++) av[i] = kT[k*68 + tc2*2+i];
            #pragma unroll
            for (int j=0;j<4;j++) bv[j] = kT[k*68 + td*4+j];
            #pragma unroll
            for (int i=0;i<2;i++)
                #pragma unroll
                for (int j=0;j<4;j++) a2[i][j] += av[i]*bv[j];
        }
        #pragma unroll
        for (int i=0;i<2;i++)
            #pragma unroll
            for (int j=0;j<4;j++){
                int c = tc2*2+i, dc = td*4+j;
                As[c*68+dc] = (dc < c) ? betas[c]*a2[i][j] : 0.f;
            }
    }
    __syncthreads();
    {
        int half = tid >> 8;
        int d = tid & 255;
        float* uc = &ucl[half*256*68 + d*68];
        if (half == 0) {
            const float* vb = g_v + ((size_t)b*LL+l0)*DD + h*DKV + d;
            for (int c=0;c<CC;c++) uc[c] = vb[(size_t)c*DD] * betas[c];
        } else {
            for (int c=0;c<CC;c++) uc[c] = betas[c]*kT[d*68+c];
        }
        for (int c=1;c<CC;c++){
            const float* Ar = &As[c*68];
            float s = 0.f;
            int cq = c >> 2;
            for (int mq=0; mq<cq; mq++){
                float4 a = *(float4*)&Ar[mq*4];
                float4 u = *(float4*)&uc[mq*4];
                s += a.x*u.x + a.y*u.y + a.z*u.z + a.w*u.w;
            }
            for (int m=cq*4; m<c; m++) s += Ar[m]*uc[m];
            uc[c] -= s;
        }
        float* dst = (half == 0) ? g_Tu : g_Tw;
        for (int c=0;c<CC;c++) dst[((size_t)bhn*CC + c)*DKV + d] = uc[c];
    }
    __syncthreads();
    {
        float t2[2][4];
        #pragma unroll
        for (int i=0;i<2;i++)
            #pragma unroll
            for (int j=0;j<4;j++) t2[i][j]=0.f;
        for (int ks=0; ks<4; ks++){
            __syncthreads();
            for (int i = tid; i < CC*64; i += 512){
                int c = i>>6, kk = i&63;
                As[c*68+kk] = g_q[((size_t)b*LL+l0+c)*DD + h*DKV + ks*64+kk];
            }
            __syncthreads();
            for (int kk=0;kk<64;kk++){
                int k = ks*64+kk;
                float av[2], bv[4];
                #pragma unroll
                for (int i=0;i<2;i++) av[i] = As[(tc2*2+i)*68 + kk];
                #pragma unroll
                for (int j=0;j<4;j++) bv[j] = kT[k*68 + td*4+j];
                #pragma unroll
                for (int i=0;i<2;i++)
                    #pragma unroll
                    for (int j=0;j<4;j++) t2[i][j] += av[i]*bv[j];
            }
        }
        #pragma unroll
        for (int i=0;i<2;i++)
            #pragma unroll
            for (int j=0;j<4;j++){
                int c = tc2*2+i, dc = td*4+j;
                g_attn[(size_t)bhn*CC*CC + c*CC + dc] = (dc <= c) ? t2[i][j] : 0.f;
            }
    }
}

// ---------------- scan v6: 512 threads, full-chunk staging, 2c x 4v phase A ----------------
__global__ __launch_bounds__(512) void scan_kernel()
{
    extern __shared__ float sm[];
    float* SfT = sm;                    // [16][260]
    float* SsT = SfT + 16*SP;           // [16][260]
    float* TwS = SsT + 16*SP;           // [64][260]  (also k)
    float* QS  = TwS + 64*SP;           // [64][260]  (also attn, stride 68)
    float* Uc  = QS + 64*SP;            // [64][20]
    float* oP  = Uc + 64*20;            // [64][20]   gated af/as partial
    int tid = threadIdx.x;
    int bh = blockIdx.x / CT, tile = blockIdx.x % CT;
    int b = bh / HH, h = bh % HH;
    int col0 = tile * TV;
    int rA = tid >> 3;                  // o_intra: c row
    int cA = (tid & 7) * 2;             // o_intra: v pair
    int kth = tid >> 1;                 // kU: k (0..255)
    int vh  = (tid & 1) * 8;            // kU: v half
    for (int i = tid; i < 16*SP; i += 512) { SfT[i]=0.f; SsT[i]=0.f; }
    __syncthreads();
    const float* qg = g_q + (size_t)b*LL*DD + h*DKV;
    const float* kg = g_k + (size_t)b*LL*DD + h*DKV;
    for (int n = 0; n < NCH; n++) {
        int bhn = bh*NCH + n;
        float psi = g_psi[bhn], gf = g_gfc[bhn], gs = g_gsc[bhn];
        size_t tbase = (size_t)bhn*CC*DKV;
        // ---- stage full Tw + q for the chunk
        for (int i = tid; i < 4096; i += 512) {
            int c = i >> 6, kq = (i & 63) * 4;
            *(float4*)&TwS[c*SP+kq] = *(const float4*)&g_Tw[tbase + (size_t)c*DKV + kq];
            *(float4*)&QS [c*SP+kq] = *(const float4*)&qg[(size_t)(n*CC+c)*DD + kq];
        }
        __syncthreads();
        // ---- phase A: 128 threads, 2c x 4v register tiles
        if (tid < 128) {
            int tc = tid >> 2, c0 = tc*2;
            int vq = (tid & 3) * 4;
            float au[2][4], af[2][4], as2[2][4];
            #pragma unroll
            for (int i=0;i<2;i++)
                #pragma unroll
                for (int e=0;e<4;e++){ au[i][e]=0.f; af[i][e]=0.f; as2[i][e]=0.f; }
            #pragma unroll 2
            for (int k4 = 0; k4 < 64; k4++) {
                int kk = k4*4;
                float4 sfv[4], ssv[4];
                #pragma unroll
                for (int e=0;e<4;e++){
                    sfv[e] = *(float4*)&SfT[(vq+e)*SP + kk];
                    ssv[e] = *(float4*)&SsT[(vq+e)*SP + kk];
                }
                float4 tw0 = *(float4*)&TwS[c0*SP + kk];
                float4 tw1 = *(float4*)&TwS[(c0+1)*SP + kk];
                float4 q0  = *(float4*)&QS[c0*SP + kk];
                float4 q1  = *(float4*)&QS[(c0+1)*SP + kk];
                #pragma unroll
                for (int e=0;e<4;e++){
                    float sfx=sfv[e].x, sfy=sfv[e].y, sfz=sfv[e].z, sfw=sfv[e].w;
                    float ssx=ssv[e].x, ssy=ssv[e].y, ssz=ssv[e].z, ssw=ssv[e].w;
                    float sx=sfx+ssx, sy=sfy+ssy, sz=sfz+ssz, sw=sfw+ssw;
                    au[0][e] -= tw0.x*sx + tw0.y*sy + tw0.z*sz + tw0.w*sw;
                    au[1][e] -= tw1.x*sx + tw1.y*sy + tw1.z*sz + tw1.w*sw;
                    af[0][e] += q0.x*sfx + q0.y*sfy + q0.z*sfz + q0.w*sfw;
                    af[1][e] += q1.x*sfx + q1.y*sfy + q1.z*sfz + q1.w*sfw;
                    as2[0][e] += q0.x*ssx + q0.y*ssy + q0.z*ssz + q0.w*ssw;
                    as2[1][e] += q1.x*ssx + q1.y*ssy + q1.z*ssz + q1.w*ssw;
                }
            }
            #pragma unroll
            for (int i=0;i<2;i++){
                int c = c0 + i;
                int l = n*CC + c;
                float gFv = g_gF[(size_t)bh*LL + l];
                float gSv = g_gS[(size_t)bh*LL + l];
                #pragma unroll
                for (int e=0;e<4;e++){
                    Uc[c*20 + vq+e] = g_Tu[tbase + (size_t)c*DKV + col0+vq+e] + au[i][e];
                    oP[c*20 + vq+e] = gFv*af[i][e] + gSv*as2[i][e];
                }
            }
        }
        __syncthreads();
        // ---- restage: attn into QS (stride 68), k into TwS (full)
        for (int i = tid; i < 1024; i += 512) {
            int c = i >> 4, kq = (i & 15) * 4;
            *(float4*)&QS[c*68+kq] = *(const float4*)&g_attn[(size_t)bhn*CC*CC + c*CC + kq];
        }
        for (int i = tid; i < 4096; i += 512) {
            int c = i >> 6, kq = (i & 63) * 4;
            *(float4*)&TwS[c*SP+kq] = *(const float4*)&kg[(size_t)(n*CC+c)*DD + kq];
        }
        __syncthreads();
        // ---- o_intra + output
        {
            float oi0=0, oi1=0;
            #pragma unroll 4
            for (int dq = 0; dq < 16; dq++) {
                float4 a = *(float4*)&QS[rA*68 + dq*4];
                float2 u0 = *(float2*)&Uc[(dq*4+0)*20 + cA];
                float2 u1 = *(float2*)&Uc[(dq*4+1)*20 + cA];
                float2 u2 = *(float2*)&Uc[(dq*4+2)*20 + cA];
                float2 u3 = *(float2*)&Uc[(dq*4+3)*20 + cA];
                oi0 += a.x*u0.x + a.y*u1.x + a.z*u2.x + a.w*u3.x;
                oi1 += a.x*u0.y + a.y*u1.y + a.z*u2.y + a.w*u3.y;
            }
            float2 op = *(float2*)&oP[rA*20 + cA];
            int l = n*CC + rA;
            *(float2*)&g_o[((size_t)bh*LL + l)*DKV + col0 + cA] =
                make_float2(op.x + oi0, op.y + oi1);
        }
        // ---- kU + state update
        {
            float psn = 1.f - psi;
            float ku[8];
            #pragma unroll
            for (int e=0;e<8;e++) ku[e]=0.f;
            #pragma unroll 8
            for (int c = 0; c < CC; c++) {
                float kv = TwS[c*SP + kth];
                float4 ua = *(float4*)&Uc[c*20 + vh];
                float4 ub = *(float4*)&Uc[c*20 + vh + 4];
                ku[0]+=kv*ua.x; ku[1]+=kv*ua.y; ku[2]+=kv*ua.z; ku[3]+=kv*ua.w;
                ku[4]+=kv*ub.x; ku[5]+=kv*ub.y; ku[6]+=kv*ub.z; ku[7]+=kv*ub.w;
            }
            #pragma unroll
            for (int e=0;e<8;e++) {
                int idx = (vh+e)*SP + kth;
                SfT[idx] = gf*SfT[idx] + psn*ku[e];
                SsT[idx] = gs*SsT[idx] + psi*ku[e];
            }
        }
        __syncthreads();
    }
}

// ---------------- gated RMSNorm + bf16 hi/lo split fused ----------------
__global__ __launch_bounds__(256) void onorm_kernel(
    const float* __restrict__ onw)
{
    __shared__ float red[8];
    int bid = blockIdx.x;
    int h = bid & 3; int bl = bid >> 2;
    int b = bl / LL, l = bl % LL;
    int v = threadIdx.x;
    float val = g_o[(((size_t)(b*HH+h))*LL + l)*DKV + v];
    float s = warp_sum(val*val);
    if ((v & 31) == 0) red[v >> 5] = s;
    __syncthreads();
    if (v < 32) {
        float t = (v < 8) ? red[v] : 0.f;
        #pragma unroll
        for (int m = 4; m > 0; m >>= 1) t += __shfl_xor_sync(0xffffffffu, t, m);
        if (v == 0) red[0] = t;
    }
    __syncthreads();
    float scale = rsqrtf(red[0]*(1.f/DKV) + 1e-5f);
    float gv = g_gp[(size_t)bl*DD + h*DKV + v];
    float out = val*scale*onw[v]*sigmoidf_(gv);
    __nv_bfloat16 hi = __float2bfloat16(out);
    size_t oi = (size_t)bl*DD + h*DKV + v;
    g_onh[oi] = hi;
    g_onl[oi] = __float2bfloat16(out - __bfloat162float(hi));
}

// ---------------- launch ----------------
extern "C" void kernel_launch(void* const* d_in, const int* in_sizes, int n_in,
                              void* d_out, int out_size)
{
    const float* x     = (const float*)d_in[0];
    const float* Wq    = (const float*)d_in[1];
    const float* Wk    = (const float*)d_in[2];
    const float* Wv    = (const float*)d_in[3];
    const float* cq_w  = (const float*)d_in[4];
    const float* cq_b  = (const float*)d_in[5];
    const float* ck_w  = (const float*)d_in[6];
    const float* ck_b  = (const float*)d_in[7];
    const float* cv_w  = (const float*)d_in[8];
    const float* cv_b  = (const float*)d_in[9];
    const float* Wb    = (const float*)d_in[10];
    const float* Wfd   = (const float*)d_in[11];
    const float* bfd   = (const float*)d_in[12];
    const float* fdb   = (const float*)d_in[13];
    const float* Wsd   = (const float*)d_in[14];
    const float* bsd   = (const float*)d_in[15];
    const float* sdb   = (const float*)d_in[16];
    const float* W_bil = (const float*)d_in[17];
    const float* temp  = (const float*)d_in[18];
    const float* fw1   = (const float*)d_in[19];
    const float* fb1   = (const float*)d_in[20];
    const float* fw2   = (const float*)d_in[21];
    const float* fb2   = (const float*)d_in[22];
    const float* Wfg   = (const float*)d_in[23];
    const float* Wsg   = (const float*)d_in[24];
    const float* Wg    = (const float*)d_in[25];
    const float* onw   = (const float*)d_in[26];
    const float* Wo    = (const float*)d_in[27];
    float* out = (float*)d_out;

    __nv_bfloat16 *p_xh,*p_xl,*p_onh,*p_onl;
    cudaGetSymbolAddress((void**)&p_xh, g_xh);
    cudaGetSymbolAddress((void**)&p_xl, g_xl);
    cudaGetSymbolAddress((void**)&p_onh, g_onh);
    cudaGetSymbolAddress((void**)&p_onl, g_onl);

    int psi_smem  = (16384+16384+520+256)*4;
    int tf_smem   = (256*68 + 64*68 + 2*256*68 + 64)*4;
    int scan_smem = (2*16*SP + 2*64*SP + 2*64*20)*4;
    cudaFuncSetAttribute(psi_kernel,      cudaFuncAttributeMaxDynamicSharedMemorySize, psi_smem);
    cudaFuncSetAttribute(tfactor_kernel,  cudaFuncAttributeMaxDynamicSharedMemorySize, tf_smem);
    cudaFuncSetAttribute(scan_kernel,     cudaFuncAttributeMaxDynamicSharedMemorySize, scan_smem);
    cudaFuncSetAttribute(gemm_proj_kernel, cudaFuncAttributeMaxDynamicSharedMemorySize, GEMM_SMEM);
    cudaFuncSetAttribute(gemm_wo_kernel,   cudaFuncAttributeMaxDynamicSharedMemorySize, GEMM_SMEM);

    smallproj_kernel<<<BLD, 256>>>(x, Wb, Wfd, bfd, fdb, Wsd, bsd, sdb, Wfg, Wsg);
    dim3 wtg(DD/32, DD/32, 5);
    wtrans_all_kernel<<<wtg, 256>>>(Wq, Wk, Wv, Wg, Wo);
    dim3 gp(GN/128, BLD/128, 4);
    gemm_proj_kernel<<<gp, 256, GEMM_SMEM>>>(p_xh, p_xl);
    dim3 cg(BLD*HH, 3);
    conv_all_kernel<<<cg, 256>>>(cq_w, cq_b, ck_w, ck_b, cv_w, cv_b);
    tfactor_kernel<<<BH*NCH, 512, tf_smem>>>();
    psi_kernel<<<BH*NCH, 256, psi_smem>>>(W_bil, temp, fw1, fb1, fw2, fb2);
    scan_kernel<<<BH*CT, 512, scan_smem>>>();
    onorm_kernel<<<BLD*HH, 256>>>(onw);
    dim3 gw(GN/128, BLD/128);
    gemm_wo_kernel<<<gw, 256, GEMM_SMEM>>>(p_onh, p_onl, out);
}

// round 17
// speedup vs baseline: 1.3245x; 1.0122x over previous
#include <cuda_runtime.h>
#include <cuda_bf16.h>
#include <math.h>
#include <stdint.h>

#define BB   2
#define LL   4096
#define DD   1024
#define HH   4
#define DKV  256
#define CC   64
#define NCH  64
#define BH   (BB*HH)
#define BLD  (BB*LL)
#define CT   16
#define TV   16
#define WSZ  ((size_t)DD*DD)
#define SP   260

// ---------------- scratch ----------------
__device__ float g_qp[BLD*DD];
__device__ float g_kp[BLD*DD];
__device__ float g_vp[BLD*DD];
__device__ float g_q [BLD*DD];
__device__ float g_k [BLD*DD];
__device__ float g_v [BLD*DD];
__device__ float g_gp[BLD*DD];
__device__ float g_beta[BH*LL];
__device__ float g_fd[BH*LL];
__device__ float g_sd[BH*LL];
__device__ float g_gF[BH*LL];
__device__ float g_gS[BH*LL];
__device__ float g_psi[BH*NCH];
__device__ float g_gfc[BH*NCH];
__device__ float g_gsc[BH*NCH];
__device__ float g_Tu[(size_t)BH*NCH*CC*DKV];
__device__ float g_Tw[(size_t)BH*NCH*CC*DKV];
__device__ float g_attn[(size_t)BH*NCH*CC*CC];
__device__ float g_o [(size_t)BH*LL*DKV];

__device__ __nv_bfloat16 g_xh[(size_t)BLD*DD];
__device__ __nv_bfloat16 g_xl[(size_t)BLD*DD];
__device__ __nv_bfloat16 g_onh[(size_t)BLD*DD];
__device__ __nv_bfloat16 g_onl[(size_t)BLD*DD];
__device__ __nv_bfloat16 g_wth[(size_t)5*DD*DD];
__device__ __nv_bfloat16 g_wtl[(size_t)5*DD*DD];

__device__ __forceinline__ float sigmoidf_(float x){ return 1.f/(1.f+expf(-x)); }
__device__ __forceinline__ float warp_sum(float v){
    #pragma unroll
    for (int m = 16; m > 0; m >>= 1) v += __shfl_xor_sync(0xffffffffu, v, m);
    return v;
}
#define CP_ASYNC16(smaddr, gptr) \
    asm volatile("cp.async.ca.shared.global [%0], [%1], 16;" :: "r"(smaddr), "l"(gptr) : "memory")
#define CP_COMMIT() asm volatile("cp.async.commit_group;" ::: "memory")
#define CP_WAIT0()  asm volatile("cp.async.wait_group 0;" ::: "memory")
#define LDSM4(r0,r1,r2,r3, addr) \
    asm volatile("ldmatrix.sync.aligned.m8n8.x4.shared.b16 {%0,%1,%2,%3}, [%4];" \
        : "=r"(r0), "=r"(r1), "=r"(r2), "=r"(r3) : "r"(addr))

// ================= mma.sync split-bf16 GEMM, cp.async + ldmatrix =================
#define GK   1024
#define GN   1024
#define SAST 40
#define GBUF (4*128*SAST)
#define GEMM_SMEM (2*GBUF*2)

#define MMA16816(d, a0, a1, a2, a3, b0, b1)                                   \
    asm volatile("mma.sync.aligned.m16n8k16.row.col.f32.bf16.bf16.f32 "       \
        "{%0,%1,%2,%3}, {%4,%5,%6,%7}, {%8,%9}, {%0,%1,%2,%3};"               \
        : "+f"(d[0]), "+f"(d[1]), "+f"(d[2]), "+f"(d[3])                      \
        : "r"(a0), "r"(a1), "r"(a2), "r"(a3), "r"(b0), "r"(b1))

__device__ __forceinline__ void gemm_fill_async(
    __nv_bfloat16* buf, uint32_t buf_sa,
    const __nv_bfloat16* Ah, const __nv_bfloat16* Al,
    const __nv_bfloat16* Bh, const __nv_bfloat16* Bl,
    int m0, int n0, int k0, int tid)
{
    #pragma unroll
    for (int it = 0; it < 2; it++) {
        int i = tid + it*256;
        int r = i >> 2, c = (i & 3) * 8;
        size_t ga = (size_t)(m0 + r)*GK + k0 + c;
        size_t gb = (size_t)(n0 + r)*GK + k0 + c;
        uint32_t so = (uint32_t)((r*SAST + c) * 2);
        CP_ASYNC16(buf_sa + 0*128*SAST*2 + so, Ah + ga);
        CP_ASYNC16(buf_sa + 1*128*SAST*2 + so, Al + ga);
        CP_ASYNC16(buf_sa + 2*128*SAST*2 + so, Bh + gb);
        CP_ASYNC16(buf_sa + 3*128*SAST*2 + so, Bl + gb);
    }
}

__device__ __forceinline__ void gemm_body(
    const __nv_bfloat16* __restrict__ Ah, const __nv_bfloat16* __restrict__ Al,
    const __nv_bfloat16* __restrict__ Bh, const __nv_bfloat16* __restrict__ Bl,
    float* __restrict__ C, __nv_bfloat16* smbase)
{
    int tid = threadIdx.x;
    int warp = tid >> 5, lane = tid & 31;
    int wm = warp >> 1, wn = warp & 1;
    int m0 = blockIdx.y * 128, n0 = blockIdx.x * 128;
    int lg = lane >> 2;
    int lt = lane & 3;
    uint32_t smb_sa = (uint32_t)__cvta_generic_to_shared(smbase);
    // ldmatrix lane mapping: row = (lane&7) + ((lane>>3)&1)*8, col-half = (lane>>4)*8
    int lrow = (lane & 7) + ((lane >> 3) & 1) * 8;
    int lcol = (lane >> 4) * 8;

    float acc[2][8][4];
    #pragma unroll
    for (int mi=0; mi<2; mi++)
        #pragma unroll
        for (int ni=0; ni<8; ni++)
            #pragma unroll
            for (int r=0; r<4; r++) acc[mi][ni][r] = 0.f;

    gemm_fill_async(smbase, smb_sa, Ah, Al, Bh, Bl, m0, n0, 0, tid);
    CP_COMMIT();

    for (int t = 0; t < GK/32; t++) {
        CP_WAIT0();
        __syncthreads();
        uint32_t bsa = smb_sa + (uint32_t)((t & 1)*GBUF*2);
        if (t + 1 < GK/32) {
            gemm_fill_async(smbase, smb_sa + ((t+1)&1)*GBUF*2,
                            Ah, Al, Bh, Bl, m0, n0, (t+1)*32, tid);
            CP_COMMIT();
        }
        uint32_t saAh = bsa;
        uint32_t saAl = bsa + 128*SAST*2;
        uint32_t saBh = bsa + 2*128*SAST*2;
        uint32_t saBl = bsa + 3*128*SAST*2;
        #pragma unroll
        for (int ks = 0; ks < 2; ks++) {
            int kt = ks*16 + lcol;
            uint32_t aH[2][4], aL[2][4];
            #pragma unroll
            for (int mi = 0; mi < 2; mi++) {
                int row0 = wm*32 + mi*16;
                uint32_t ao = (uint32_t)(((row0 + lrow)*SAST + kt) * 2);
                LDSM4(aH[mi][0], aH[mi][1], aH[mi][2], aH[mi][3], saAh + ao);
                LDSM4(aL[mi][0], aL[mi][1], aL[mi][2], aL[mi][3], saAl + ao);
            }
            #pragma unroll
            for (int ni2 = 0; ni2 < 4; ni2++) {
                int nr0 = wn*64 + ni2*16;
                uint32_t bo = (uint32_t)(((nr0 + lrow)*SAST + kt) * 2);
                uint32_t bh4[4], bl4[4];
                LDSM4(bh4[0], bh4[1], bh4[2], bh4[3], saBh + bo);
                LDSM4(bl4[0], bl4[1], bl4[2], bl4[3], saBl + bo);
                #pragma unroll
                for (int no = 0; no < 2; no++) {
                    int ni = ni2*2 + no;
                    uint32_t bh0 = bh4[no], bh1 = bh4[no+2];
                    uint32_t bl0 = bl4[no], bl1 = bl4[no+2];
                    #pragma unroll
                    for (int mi = 0; mi < 2; mi++) {
                        MMA16816(acc[mi][ni], aH[mi][0],aH[mi][1],aH[mi][2],aH[mi][3], bh0, bh1);
                        MMA16816(acc[mi][ni], aH[mi][0],aH[mi][1],aH[mi][2],aH[mi][3], bl0, bl1);
                        MMA16816(acc[mi][ni], aL[mi][0],aL[mi][1],aL[mi][2],aL[mi][3], bh0, bh1);
                    }
                }
            }
        }
        __syncthreads();
    }
    #pragma unroll
    for (int mi = 0; mi < 2; mi++) {
        int row = m0 + wm*32 + mi*16 + lg;
        #pragma unroll
        for (int ni = 0; ni < 8; ni++) {
            int col = n0 + wn*64 + ni*8 + lt*2;
            *(float2*)&C[(size_t)row*GN + col]     = make_float2(acc[mi][ni][0], acc[mi][ni][1]);
            *(float2*)&C[(size_t)(row+8)*GN + col] = make_float2(acc[mi][ni][2], acc[mi][ni][3]);
        }
    }
}

__global__ __launch_bounds__(256, 2) void gemm_proj_kernel(
    const __nv_bfloat16* __restrict__ Ah, const __nv_bfloat16* __restrict__ Al)
{
    extern __shared__ float sm[];
    int z = blockIdx.z;
    float* C = (z==0) ? g_qp : (z==1) ? g_kp : (z==2) ? g_vp : g_gp;
    gemm_body(Ah, Al, g_wth + (size_t)z*WSZ, g_wtl + (size_t)z*WSZ, C, (__nv_bfloat16*)sm);
}

__global__ __launch_bounds__(256, 2) void gemm_wo_kernel(
    const __nv_bfloat16* __restrict__ Ah, const __nv_bfloat16* __restrict__ Al,
    float* __restrict__ C)
{
    extern __shared__ float sm[];
    gemm_body(Ah, Al, g_wth + 4*WSZ, g_wtl + 4*WSZ, C, (__nv_bfloat16*)sm);
}

// ---------------- fused weight transpose+split ----------------
__global__ __launch_bounds__(256) void wtrans_all_kernel(
    const float* __restrict__ W0, const float* __restrict__ W1,
    const float* __restrict__ W2, const float* __restrict__ W3,
    const float* __restrict__ W4)
{
    __shared__ float t[32][33];
    int z = blockIdx.z;
    const float* W = (z==0)?W0 : (z==1)?W1 : (z==2)?W2 : (z==3)?W3 : W4;
    __nv_bfloat16* Th = g_wth + (size_t)z*WSZ;
    __nv_bfloat16* Tl = g_wtl + (size_t)z*WSZ;
    int n0 = blockIdx.x*32, k0 = blockIdx.y*32;
    int tx = threadIdx.x & 31, ty0 = threadIdx.x >> 5;
    #pragma unroll
    for (int r = 0; r < 4; r++) {
        int ty = ty0 + r*8;
        t[ty][tx] = W[(size_t)(k0+ty)*DD + n0 + tx];
    }
    __syncthreads();
    #pragma unroll
    for (int r = 0; r < 4; r++) {
        int ty = ty0 + r*8;
        float v = t[tx][ty];
        __nv_bfloat16 h = __float2bfloat16(v);
        Th[(size_t)(n0+ty)*DD + k0+tx] = h;
        Tl[(size_t)(n0+ty)*DD + k0+tx] = __float2bfloat16(v - __bfloat162float(h));
    }
}

// ---------------- fused depthwise conv ----------------
__global__ __launch_bounds__(256) void conv_all_kernel(
    const float* __restrict__ wq, const float* __restrict__ bq,
    const float* __restrict__ wk, const float* __restrict__ bk,
    const float* __restrict__ wv, const float* __restrict__ bv)
{
    __shared__ float red[8];
    int which = blockIdx.y;
    const float* P    = (which==0) ? g_qp : (which==1) ? g_kp : g_vp;
    float*       outp = (which==0) ? g_q  : (which==1) ? g_k  : g_v;
    const float* w    = (which==0) ? wq : (which==1) ? wk : wv;
    const float* bias = (which==0) ? bq : (which==1) ? bk : bv;
    int do_norm = (which < 2);
    int bid = blockIdx.x;
    int h = bid & 3; int bl = bid >> 2;
    int b = bl / LL, l = bl % LL;
    int ch = h*DKV + threadIdx.x;
    float4 wvv = *(const float4*)(w + (size_t)ch*4);
    const float wj[4] = {wvv.x, wvv.y, wvv.z, wvv.w};
    float val = bias[ch];
    #pragma unroll
    for (int j=0;j<4;j++) {
        int lp = l + j - 2;
        float xv = (lp>=0 && lp<LL) ? P[((size_t)b*LL+lp)*DD + ch] : 0.f;
        val += wj[j]*xv;
    }
    val = val * sigmoidf_(val);
    if (do_norm) {
        float s = warp_sum(val*val);
        if ((threadIdx.x & 31) == 0) red[threadIdx.x >> 5] = s;
        __syncthreads();
        if (threadIdx.x < 32) {
            float t = (threadIdx.x < 8) ? red[threadIdx.x] : 0.f;
            #pragma unroll
            for (int m = 4; m > 0; m >>= 1) t += __shfl_xor_sync(0xffffffffu, t, m);
            if (threadIdx.x == 0) red[0] = t;
        }
        __syncthreads();
        val = val / fmaxf(sqrtf(red[0]), 1e-6f);
    }
    outp[((size_t)b*LL+l)*DD + ch] = val;
}

// ---------------- smallproj + x hi/lo split fused ----------------
__global__ __launch_bounds__(256) void smallproj_kernel(
    const float* __restrict__ x,
    const float* __restrict__ Wb, const float* __restrict__ Wfd,
    const float* __restrict__ bfd, const float* __restrict__ fd_bias,
    const float* __restrict__ Wsd, const float* __restrict__ bsd, const float* __restrict__ sd_bias,
    const float* __restrict__ Wfg, const float* __restrict__ Wsg)
{
    __shared__ float red[8][20];
    int bl = blockIdx.x;
    int tid = threadIdx.x;
    int d0 = tid * 4;
    float4 xv = *(const float4*)&x[(size_t)bl*DD + d0];
    {
        __nv_bfloat16 h0 = __float2bfloat16(xv.x), h1 = __float2bfloat16(xv.y),
                      h2 = __float2bfloat16(xv.z), h3 = __float2bfloat16(xv.w);
        __nv_bfloat162* H2 = (__nv_bfloat162*)&g_xh[(size_t)bl*DD + d0];
        __nv_bfloat162* L2 = (__nv_bfloat162*)&g_xl[(size_t)bl*DD + d0];
        H2[0] = __nv_bfloat162(h0, h1);
        H2[1] = __nv_bfloat162(h2, h3);
        L2[0] = __nv_bfloat162(__float2bfloat16(xv.x - __bfloat162float(h0)),
                               __float2bfloat16(xv.y - __bfloat162float(h1)));
        L2[1] = __nv_bfloat162(__float2bfloat16(xv.z - __bfloat162float(h2)),
                               __float2bfloat16(xv.w - __bfloat162float(h3)));
    }
    float acc[20];
    #pragma unroll
    for (int j=0;j<20;j++) acc[j]=0.f;
    float xs[4] = {xv.x, xv.y, xv.z, xv.w};
    #pragma unroll
    for (int e=0;e<4;e++) {
        int d = d0 + e;
        #pragma unroll
        for (int h=0; h<4; h++) {
            acc[0*4+h] += xs[e] * Wb [d*4+h];
            acc[1*4+h] += xs[e] * Wfd[d*4+h];
            acc[2*4+h] += xs[e] * Wsd[d*4+h];
            acc[3*4+h] += xs[e] * Wfg[d*4+h];
            acc[4*4+h] += xs[e] * Wsg[d*4+h];
        }
    }
    #pragma unroll
    for (int j=0;j<20;j++) {
        float s = warp_sum(acc[j]);
        if ((tid & 31) == 0) red[tid >> 5][j] = s;
    }
    __syncthreads();
    if (tid < 20) {
        float s = 0.f;
        #pragma unroll
        for (int w = 0; w < 8; w++) s += red[w][tid];
        int p = tid/4, h = tid%4;
        int b = bl / LL, l = bl % LL;
        size_t oi = ((size_t)(b*HH + h))*LL + l;
        if      (p==0) g_beta[oi] = sigmoidf_(s);
        else if (p==1) g_fd[oi]   = sigmoidf_(s + bfd[h] + fd_bias[h]);
        else if (p==2) g_sd[oi]   = sigmoidf_(s + bsd[h] + sd_bias[h]);
        else if (p==3) g_gF[oi]   = sigmoidf_(s);
        else           g_gS[oi]   = sigmoidf_(s);
    }
}

// ---------------- psi (R12) ----------------
__global__ __launch_bounds__(256) void psi_kernel(
    const float* __restrict__ W_bil, const float* __restrict__ temp,
    const float* __restrict__ fw1, const float* __restrict__ fb1,
    const float* __restrict__ fw2, const float* __restrict__ fb2)
{
    extern __shared__ float sm[];
    float* kcs  = sm;
    float* us   = sm + 16384;
    float* flux = sm + 32768;
    float* red  = sm + 32768 + 520;
    int bhn = blockIdx.x;
    int n = bhn % NCH; int bh = bhn / NCH; int b = bh / HH, h = bh % HH;
    int tid = threadIdx.x;
    int l0 = n*CC;
    for (int i = tid; i < CC*DKV; i += 256) {
        int c = i >> 8, d = i & 255;
        size_t gi = ((size_t)b*LL + l0 + c)*DD + h*DKV + d;
        float bta = g_beta[(size_t)bh*LL + l0 + c];
        kcs[i] = g_k[gi];
        us[i]  = g_v[gi] * bta;
    }
    __syncthreads();
    int d = tid;
    float km=0.f, um=0.f;
    for (int c=0;c<CC;c++){ km += kcs[c*256+d]; um += us[c*256+d]; }
    flux[d]     = km * (1.f/CC);
    flux[256+d] = um * (1.f/CC);
    const float* W = W_bil + (size_t)h*DKV*DKV;
    float bsum = 0.f;
    for (int c0 = 0; c0 < CC; c0 += 16) {
        float dot[16];
        #pragma unroll
        for (int c2=0;c2<16;c2++) dot[c2]=0.f;
        for (int k4 = 0; k4 < 64; k4++) {
            float wv0 = W[(size_t)(k4*4+0)*DKV + d];
            float wv1 = W[(size_t)(k4*4+1)*DKV + d];
            float wv2 = W[(size_t)(k4*4+2)*DKV + d];
            float wv3 = W[(size_t)(k4*4+3)*DKV + d];
            #pragma unroll
            for (int c2=0;c2<16;c2++){
                float4 kc = *(float4*)&kcs[(c0+c2)*256 + k4*4];
                dot[c2] += kc.x*wv0 + kc.y*wv1 + kc.z*wv2 + kc.w*wv3;
            }
        }
        #pragma unroll
        for (int c2=0;c2<16;c2++) bsum += dot[c2] * us[(c0+c2)*256 + d];
    }
    red[tid] = bsum; __syncthreads();
    for (int s=128;s>0;s>>=1){ if(tid<s) red[tid]+=red[tid+s]; __syncthreads(); }
    if (tid==0) flux[512] = red[0] / (temp[h] * (float)CC);
    __syncthreads();
    float hj = 0.f;
    if (tid < 128) {
        float a = fb1[tid];
        for (int i=0;i<513;i++) a += flux[i]*fw1[i*128+tid];
        a = a * sigmoidf_(a);
        hj = a * fw2[tid];
    }
    red[tid] = hj; __syncthreads();
    for (int s=128;s>0;s>>=1){ if(tid<s) red[tid]+=red[tid+s]; __syncthreads(); }
    if (tid == 0) {
        float p = sigmoidf_(red[0] + fb2[0]);
        g_psi[bhn] = fminf(fmaxf(p, 0.01f), 0.99f);
    }
    __syncthreads();
    red[tid] = (tid<CC) ? logf(g_fd[(size_t)bh*LL + l0 + tid]) : 0.f;
    __syncthreads();
    for (int s=128;s>0;s>>=1){ if(tid<s) red[tid]+=red[tid+s]; __syncthreads(); }
    if (tid==0) g_gfc[bhn] = expf(red[0]);
    __syncthreads();
    red[tid] = (tid<CC) ? logf(g_sd[(size_t)bh*LL + l0 + tid]) : 0.f;
    __syncthreads();
    for (int s=128;s>0;s>>=1){ if(tid<s) red[tid]+=red[tid+s]; __syncthreads(); }
    if (tid==0) g_gsc[bhn] = expf(red[0]);
}

// ---------------- tfactor v4 (R14) ----------------
__global__ __launch_bounds__(512) void tfactor_kernel()
{
    extern __shared__ float sm[];
    float* kT    = sm;                      // [256][68]
    float* As    = sm + 256*68;             // [64][68]
    float* ucl   = As + 64*68;              // [2][256][68]
    float* betas = ucl + 2*256*68;          // [64]
    int bhn = blockIdx.x;
    int n = bhn % NCH, bh = bhn/NCH, b = bh/HH, h = bh%HH;
    int l0 = n*CC, tid = threadIdx.x;
    int tc2 = tid >> 4, td = tid & 15;

    for (int i = tid; i < CC*DKV; i += 512) {
        int c = i >> 8, dk = i & 255;
        kT[dk*68 + c] = g_k[((size_t)b*LL + l0 + c)*DD + h*DKV + dk];
    }
    if (tid < CC) betas[tid] = g_beta[(size_t)bh*LL + l0 + tid];
    __syncthreads();
    {
        float a2[2][4];
        #pragma unroll
        for (int i=0;i<2;i++)
            #pragma unroll
            for (int j=0;j<4;j++) a2[i][j]=0.f;
        for (int k=0;k<DKV;k++){
            float av[2], bv[4];
            #pragma unroll
            for (int i=0;i<2;i++) av[i] = kT[k*68 + tc2*2+i];
            #pragma unroll
            for (int j=0;j<4;j++) bv[j] = kT[k*68 + td*4+j];
            #pragma unroll
            for (int i=0;i<2;i++)
                #pragma unroll
                for (int j=0;j<4;j++) a2[i][j] += av[i]*bv[j];
        }
        #pragma unroll
        for (int i=0;i<2;i++)
            #pragma unroll
            for (int j=0;j<4;j++){
                int c = tc2*2+i, dc = td*4+j;
                As[c*68+dc] = (dc < c) ? betas[c]*a2[i][j] : 0.f;
            }
    }
    __syncthreads();
    {
        int half = tid >> 8;
        int d = tid & 255;
        float* uc = &ucl[half*256*68 + d*68];
        if (half == 0) {
            const float* vb = g_v + ((size_t)b*LL+l0)*DD + h*DKV + d;
            for (int c=0;c<CC;c++) uc[c] = vb[(size_t)c*DD] * betas[c];
        } else {
            for (int c=0;c<CC;c++) uc[c] = betas[c]*kT[d*68+c];
        }
        for (int c=1;c<CC;c++){
            const float* Ar = &As[c*68];
            float s = 0.f;
            int cq = c >> 2;
            for (int mq=0; mq<cq; mq++){
                float4 a = *(float4*)&Ar[mq*4];
                float4 u = *(float4*)&uc[mq*4];
                s += a.x*u.x + a.y*u.y + a.z*u.z + a.w*u.w;
            }
            for (int m=cq*4; m<c; m++) s += Ar[m]*uc[m];
            uc[c] -= s;
        }
        float* dst = (half == 0) ? g_Tu : g_Tw;
        for (int c=0;c<CC;c++) dst[((size_t)bhn*CC + c)*DKV + d] = uc[c];
    }
    __syncthreads();
    {
        float t2[2][4];
        #pragma unroll
        for (int i=0;i<2;i++)
            #pragma unroll
            for (int j=0;j<4;j++) t2[i][j]=0.f;
        for (int ks=0; ks<4; ks++){
            __syncthreads();
            for (int i = tid; i < CC*64; i += 512){
                int c = i>>6, kk = i&63;
                As[c*68+kk] = g_q[((size_t)b*LL+l0+c)*DD + h*DKV + ks*64+kk];
            }
            __syncthreads();
            for (int kk=0;kk<64;kk++){
                int k = ks*64+kk;
                float av[2], bv[4];
                #pragma unroll
                for (int i=0;i<2;i++) av[i] = As[(tc2*2+i)*68 + kk];
                #pragma unroll
                for (int j=0;j<4;j++) bv[j] = kT[k*68 + td*4+j];
                #pragma unroll
                for (int i=0;i<2;i++)
                    #pragma unroll
                    for (int j=0;j<4;j++) t2[i][j] += av[i]*bv[j];
            }
        }
        #pragma unroll
        for (int i=0;i<2;i++)
            #pragma unroll
            for (int j=0;j<4;j++){
                int c = tc2*2+i, dc = td*4+j;
                g_attn[(size_t)bhn*CC*CC + c*CC + dc] = (dc <= c) ? t2[i][j] : 0.f;
            }
    }
}

// ---------------- scan v7: v6 + 4k x 2v kU ----------------
__global__ __launch_bounds__(512) void scan_kernel()
{
    extern __shared__ float sm[];
    float* SfT = sm;                    // [16][260]
    float* SsT = SfT + 16*SP;           // [16][260]
    float* TwS = SsT + 16*SP;           // [64][260]  (also k)
    float* QS  = TwS + 64*SP;           // [64][260]  (also attn, stride 68)
    float* Uc  = QS + 64*SP;            // [64][20]
    float* oP  = Uc + 64*20;            // [64][20]
    int tid = threadIdx.x;
    int bh = blockIdx.x / CT, tile = blockIdx.x % CT;
    int b = bh / HH, h = bh % HH;
    int col0 = tile * TV;
    int rA = tid >> 3;                  // o_intra: c row
    int cA = (tid & 7) * 2;             // o_intra: v pair
    int kq4 = (tid >> 3) * 4;           // kU: k quad base (0..252)
    int vp2 = (tid & 7) * 2;            // kU: v pair
    for (int i = tid; i < 16*SP; i += 512) { SfT[i]=0.f; SsT[i]=0.f; }
    __syncthreads();
    const float* qg = g_q + (size_t)b*LL*DD + h*DKV;
    const float* kg = g_k + (size_t)b*LL*DD + h*DKV;
    for (int n = 0; n < NCH; n++) {
        int bhn = bh*NCH + n;
        float psi = g_psi[bhn], gf = g_gfc[bhn], gs = g_gsc[bhn];
        size_t tbase = (size_t)bhn*CC*DKV;
        // ---- stage full Tw + q
        for (int i = tid; i < 4096; i += 512) {
            int c = i >> 6, kq = (i & 63) * 4;
            *(float4*)&TwS[c*SP+kq] = *(const float4*)&g_Tw[tbase + (size_t)c*DKV + kq];
            *(float4*)&QS [c*SP+kq] = *(const float4*)&qg[(size_t)(n*CC+c)*DD + kq];
        }
        __syncthreads();
        // ---- phase A: 128 threads, 2c x 4v register tiles
        if (tid < 128) {
            int tc = tid >> 2, c0 = tc*2;
            int vq = (tid & 3) * 4;
            float au[2][4], af[2][4], as2[2][4];
            #pragma unroll
            for (int i=0;i<2;i++)
                #pragma unroll
                for (int e=0;e<4;e++){ au[i][e]=0.f; af[i][e]=0.f; as2[i][e]=0.f; }
            #pragma unroll 2
            for (int k4 = 0; k4 < 64; k4++) {
                int kk = k4*4;
                float4 sfv[4], ssv[4];
                #pragma unroll
                for (int e=0;e<4;e++){
                    sfv[e] = *(float4*)&SfT[(vq+e)*SP + kk];
                    ssv[e] = *(float4*)&SsT[(vq+e)*SP + kk];
                }
                float4 tw0 = *(float4*)&TwS[c0*SP + kk];
                float4 tw1 = *(float4*)&TwS[(c0+1)*SP + kk];
                float4 q0  = *(float4*)&QS[c0*SP + kk];
                float4 q1  = *(float4*)&QS[(c0+1)*SP + kk];
                #pragma unroll
                for (int e=0;e<4;e++){
                    float sfx=sfv[e].x, sfy=sfv[e].y, sfz=sfv[e].z, sfw=sfv[e].w;
                    float ssx=ssv[e].x, ssy=ssv[e].y, ssz=ssv[e].z, ssw=ssv[e].w;
                    float sx=sfx+ssx, sy=sfy+ssy, sz=sfz+ssz, sw=sfw+ssw;
                    au[0][e] -= tw0.x*sx + tw0.y*sy + tw0.z*sz + tw0.w*sw;
                    au[1][e] -= tw1.x*sx + tw1.y*sy + tw1.z*sz + tw1.w*sw;
                    af[0][e] += q0.x*sfx + q0.y*sfy + q0.z*sfz + q0.w*sfw;
                    af[1][e] += q1.x*sfx + q1.y*sfy + q1.z*sfz + q1.w*sfw;
                    as2[0][e] += q0.x*ssx + q0.y*ssy + q0.z*ssz + q0.w*ssw;
                    as2[1][e] += q1.x*ssx + q1.y*ssy + q1.z*ssz + q1.w*ssw;
                }
            }
            #pragma unroll
            for (int i=0;i<2;i++){
                int c = c0 + i;
                int l = n*CC + c;
                float gFv = g_gF[(size_t)bh*LL + l];
                float gSv = g_gS[(size_t)bh*LL + l];
                #pragma unroll
                for (int e=0;e<4;e++){
                    Uc[c*20 + vq+e] = g_Tu[tbase + (size_t)c*DKV + col0+vq+e] + au[i][e];
                    oP[c*20 + vq+e] = gFv*af[i][e] + gSv*as2[i][e];
                }
            }
        }
        __syncthreads();
        // ---- restage: attn into QS (stride 68), k into TwS
        for (int i = tid; i < 1024; i += 512) {
            int c = i >> 4, kq = (i & 15) * 4;
            *(float4*)&QS[c*68+kq] = *(const float4*)&g_attn[(size_t)bhn*CC*CC + c*CC + kq];
        }
        for (int i = tid; i < 4096; i += 512) {
            int c = i >> 6, kq = (i & 63) * 4;
            *(float4*)&TwS[c*SP+kq] = *(const float4*)&kg[(size_t)(n*CC+c)*DD + kq];
        }
        __syncthreads();
        // ---- o_intra + output
        {
            float oi0=0, oi1=0;
            #pragma unroll 4
            for (int dq = 0; dq < 16; dq++) {
                float4 a = *(float4*)&QS[rA*68 + dq*4];
                float2 u0 = *(float2*)&Uc[(dq*4+0)*20 + cA];
                float2 u1 = *(float2*)&Uc[(dq*4+1)*20 + cA];
                float2 u2 = *(float2*)&Uc[(dq*4+2)*20 + cA];
                float2 u3 = *(float2*)&Uc[(dq*4+3)*20 + cA];
                oi0 += a.x*u0.x + a.y*u1.x + a.z*u2.x + a.w*u3.x;
                oi1 += a.x*u0.y + a.y*u1.y + a.z*u2.y + a.w*u3.y;
            }
            float2 op = *(float2*)&oP[rA*20 + cA];
            int l = n*CC + rA;
            *(float2*)&g_o[((size_t)bh*LL + l)*DKV + col0 + cA] =
                make_float2(op.x + oi0, op.y + oi1);
        }
        // ---- kU + state update: thread = 4k x 2v
        {
            float psn = 1.f - psi;
            float ku0[4], ku1[4];
            #pragma unroll
            for (int e=0;e<4;e++){ ku0[e]=0.f; ku1[e]=0.f; }
            #pragma unroll 8
            for (int c = 0; c < CC; c++) {
                float4 kv = *(float4*)&TwS[c*SP + kq4];
                float2 u2 = *(float2*)&Uc[c*20 + vp2];
                ku0[0]+=kv.x*u2.x; ku0[1]+=kv.y*u2.x; ku0[2]+=kv.z*u2.x; ku0[3]+=kv.w*u2.x;
                ku1[0]+=kv.x*u2.y; ku1[1]+=kv.y*u2.y; ku1[2]+=kv.z*u2.y; ku1[3]+=kv.w*u2.y;
            }
            {
                int i0 = vp2*SP + kq4;
                float4 sf = *(float4*)&SfT[i0];
                float4 ss = *(float4*)&SsT[i0];
                sf.x = gf*sf.x + psn*ku0[0]; sf.y = gf*sf.y + psn*ku0[1];
                sf.z = gf*sf.z + psn*ku0[2]; sf.w = gf*sf.w + psn*ku0[3];
                ss.x = gs*ss.x + psi*ku0[0]; ss.y = gs*ss.y + psi*ku0[1];
                ss.z = gs*ss.z + psi*ku0[2]; ss.w = gs*ss.w + psi*ku0[3];
                *(float4*)&SfT[i0] = sf;
                *(float4*)&SsT[i0] = ss;
                int i1 = (vp2+1)*SP + kq4;
                float4 sf1 = *(float4*)&SfT[i1];
                float4 ss1 = *(float4*)&SsT[i1];
                sf1.x = gf*sf1.x + psn*ku1[0]; sf1.y = gf*sf1.y + psn*ku1[1];
                sf1.z = gf*sf1.z + psn*ku1[2]; sf1.w = gf*sf1.w + psn*ku1[3];
                ss1.x = gs*ss1.x + psi*ku1[0]; ss1.y = gs*ss1.y + psi*ku1[1];
                ss1.z = gs*ss1.z + psi*ku1[2]; ss1.w = gs*ss1.w + psi*ku1[3];
                *(float4*)&SfT[i1] = sf1;
                *(float4*)&SsT[i1] = ss1;
            }
        }
        __syncthreads();
    }
}

// ---------------- gated RMSNorm + bf16 hi/lo split fused ----------------
__global__ __launch_bounds__(256) void onorm_kernel(
    const float* __restrict__ onw)
{
    __shared__ float red[8];
    int bid = blockIdx.x;
    int h = bid & 3; int bl = bid >> 2;
    int b = bl / LL, l = bl % LL;
    int v = threadIdx.x;
    float val = g_o[(((size_t)(b*HH+h))*LL + l)*DKV + v];
    float s = warp_sum(val*val);
    if ((v & 31) == 0) red[v >> 5] = s;
    __syncthreads();
    if (v < 32) {
        float t = (v < 8) ? red[v] : 0.f;
        #pragma unroll
        for (int m = 4; m > 0; m >>= 1) t += __shfl_xor_sync(0xffffffffu, t, m);
        if (v == 0) red[0] = t;
    }
    __syncthreads();
    float scale = rsqrtf(red[0]*(1.f/DKV) + 1e-5f);
    float gv = g_gp[(size_t)bl*DD + h*DKV + v];
    float out = val*scale*onw[v]*sigmoidf_(gv);
    __nv_bfloat16 hi = __float2bfloat16(out);
    size_t oi = (size_t)bl*DD + h*DKV + v;
    g_onh[oi] = hi;
    g_onl[oi] = __float2bfloat16(out - __bfloat162float(hi));
}

// ---------------- launch ----------------
extern "C" void kernel_launch(void* const* d_in, const int* in_sizes, int n_in,
                              void* d_out, int out_size)
{
    const float* x     = (const float*)d_in[0];
    const float* Wq    = (const float*)d_in[1];
    const float* Wk    = (const float*)d_in[2];
    const float* Wv    = (const float*)d_in[3];
    const float* cq_w  = (const float*)d_in[4];
    const float* cq_b  = (const float*)d_in[5];
    const float* ck_w  = (const float*)d_in[6];
    const float* ck_b  = (const float*)d_in[7];
    const float* cv_w  = (const float*)d_in[8];
    const float* cv_b  = (const float*)d_in[9];
    const float* Wb    = (const float*)d_in[10];
    const float* Wfd   = (const float*)d_in[11];
    const float* bfd   = (const float*)d_in[12];
    const float* fdb   = (const float*)d_in[13];
    const float* Wsd   = (const float*)d_in[14];
    const float* bsd   = (const float*)d_in[15];
    const float* sdb   = (const float*)d_in[16];
    const float* W_bil = (const float*)d_in[17];
    const float* temp  = (const float*)d_in[18];
    const float* fw1   = (const float*)d_in[19];
    const float* fb1   = (const float*)d_in[20];
    const float* fw2   = (const float*)d_in[21];
    const float* fb2   = (const float*)d_in[22];
    const float* Wfg   = (const float*)d_in[23];
    const float* Wsg   = (const float*)d_in[24];
    const float* Wg    = (const float*)d_in[25];
    const float* onw   = (const float*)d_in[26];
    const float* Wo    = (const float*)d_in[27];
    float* out = (float*)d_out;

    __nv_bfloat16 *p_xh,*p_xl,*p_onh,*p_onl;
    cudaGetSymbolAddress((void**)&p_xh, g_xh);
    cudaGetSymbolAddress((void**)&p_xl, g_xl);
    cudaGetSymbolAddress((void**)&p_onh, g_onh);
    cudaGetSymbolAddress((void**)&p_onl, g_onl);

    int psi_smem  = (16384+16384+520+256)*4;
    int tf_smem   = (256*68 + 64*68 + 2*256*68 + 64)*4;
    int scan_smem = (2*16*SP + 2*64*SP + 2*64*20)*4;
    cudaFuncSetAttribute(psi_kernel,      cudaFuncAttributeMaxDynamicSharedMemorySize, psi_smem);
    cudaFuncSetAttribute(tfactor_kernel,  cudaFuncAttributeMaxDynamicSharedMemorySize, tf_smem);
    cudaFuncSetAttribute(scan_kernel,     cudaFuncAttributeMaxDynamicSharedMemorySize, scan_smem);
    cudaFuncSetAttribute(gemm_proj_kernel, cudaFuncAttributeMaxDynamicSharedMemorySize, GEMM_SMEM);
    cudaFuncSetAttribute(gemm_wo_kernel,   cudaFuncAttributeMaxDynamicSharedMemorySize, GEMM_SMEM);

    smallproj_kernel<<<BLD, 256>>>(x, Wb, Wfd, bfd, fdb, Wsd, bsd, sdb, Wfg, Wsg);
    dim3 wtg(DD/32, DD/32, 5);
    wtrans_all_kernel<<<wtg, 256>>>(Wq, Wk, Wv, Wg, Wo);
    dim3 gp(GN/128, BLD/128, 4);
    gemm_proj_kernel<<<gp, 256, GEMM_SMEM>>>(p_xh, p_xl);
    dim3 cg(BLD*HH, 3);
    conv_all_kernel<<<cg, 256>>>(cq_w, cq_b, ck_w, ck_b, cv_w, cv_b);
    tfactor_kernel<<<BH*NCH, 512, tf_smem>>>();
    psi_kernel<<<BH*NCH, 256, psi_smem>>>(W_bil, temp, fw1, fb1, fw2, fb2);
    scan_kernel<<<BH*CT, 512, scan_smem>>>();
    onorm_kernel<<<BLD*HH, 256>>>(onw);
    dim3 gw(GN/128, BLD/128);
    gemm_wo_kernel<<<gw, 256, GEMM_SMEM>>>(p_onh, p_onl, out);
}